// round 12
// baseline (speedup 1.0000x reference)
#include <cuda_runtime.h>
#include <cuda_bf16.h>
#include <cstdint>

namespace {

constexpr float ALPHA_C = 0.01f;
typedef __nv_bfloat16 bf;
typedef signed char s8;

__device__ __align__(1024) unsigned char g_pool[200u * 1024u * 1024u];

__device__ __forceinline__ uint32_t smem_u32(const void* p) {
    uint32_t a;
    asm("{ .reg .u64 t; cvta.to.shared.u64 t, %1; cvt.u32.u64 %0, t; }" : "=r"(a) : "l"(p));
    return a;
}
__device__ __forceinline__ void cp16(uint32_t s, const void* g) {
    asm volatile("cp.async.cg.shared.global [%0], [%1], 16;" :: "r"(s), "l"(g) : "memory");
}
#define CP_COMMIT() asm volatile("cp.async.commit_group;" ::: "memory")
#define LDSMX4(r, addr) \
    asm volatile("ldmatrix.sync.aligned.m8n8.x4.shared.b16 {%0,%1,%2,%3}, [%4];" \
        : "=r"((r)[0]), "=r"((r)[1]), "=r"((r)[2]), "=r"((r)[3]) : "r"(addr))
#define LDSMX4T(r, addr) \
    asm volatile("ldmatrix.sync.aligned.m8n8.x4.trans.shared.b16 {%0,%1,%2,%3}, [%4];" \
        : "=r"((r)[0]), "=r"((r)[1]), "=r"((r)[2]), "=r"((r)[3]) : "r"(addr))
#define MMA(c, a, b0, b1) \
    asm volatile("mma.sync.aligned.m16n8k16.row.col.f32.bf16.bf16.f32 " \
        "{%0,%1,%2,%3}, {%4,%5,%6,%7}, {%8,%9}, {%0,%1,%2,%3};" \
        : "+f"((c)[0]), "+f"((c)[1]), "+f"((c)[2]), "+f"((c)[3]) \
        : "r"((a)[0]), "r"((a)[1]), "r"((a)[2]), "r"((a)[3]), "r"(b0), "r"(b1))
#define MMAS8(c, a, b0, b1) \
    asm volatile("mma.sync.aligned.m16n8k32.row.col.s32.s8.s8.s32 " \
        "{%0,%1,%2,%3}, {%4,%5,%6,%7}, {%8,%9}, {%0,%1,%2,%3};" \
        : "+r"((c)[0]), "+r"((c)[1]), "+r"((c)[2]), "+r"((c)[3]) \
        : "r"((a)[0]), "r"((a)[1]), "r"((a)[2]), "r"((a)[3]), "r"(b0), "r"(b1))

__device__ __forceinline__ void qsplit(float v, float invS, s8& q1, s8& q2) {
    int V = __float2int_rn(v * invS);
    V = max(-32512, min(32512, V));
    int lo = ((V + 128) & 255) - 128;
    q1 = (s8)((V - lo) >> 8);
    q2 = (s8)lo;
}

// ---------------- Cayley expansion (validated) ----------------
struct ExpandJobs {
    const float* W[4]; float* out[4];
    int J[4], I[4], rev[4]; float sgn[4]; int start[5];
};
__device__ __forceinline__ int reorder_sign(int a, int b) {
    int s = 0; int aa = a >> 1;
    while (aa) { s += __popc(aa & b); aa >>= 1; }
    return (s & 1) ? -1 : 1;
}
__global__ void expand_fused(ExpandJobs E)
{
    int blk = blockIdx.x, jb = 0;
#pragma unroll
    for (int t = 1; t < 4; ++t) if (blk >= E.start[t]) jb = t;
    int J = E.J[jb], I = E.I[jb];
    int idx = (blk - E.start[jb]) * 256 + threadIdx.x;
    int ncol = I * 8;
    int col = idx % ncol, row = idx / ncol;
    int a = row & 7, j = row >> 3, c = col & 7, i = col >> 3, e = a ^ c;
    float s = (float)reorder_sign(a, e) * E.sgn[jb];
    size_t widx;
    if (E.rev[jb]) {
        int k = __popc(e);
        if ((k * (k - 1) / 2) & 1) s = -s;
        widx = (size_t)j * ncol + (size_t)i * 8 + e;
    } else {
        widx = (size_t)i * (size_t)(J * 8) + (size_t)j * 8 + e;
    }
    E.out[jb][idx] = s * E.W[jb][widx];
}

// ---------------- fp32 -> bf16 hi/lo packer ----------------
struct PackJobs {
    const float* src[7]; bf* hi[7]; bf* lo[7]; int start[8];
};
__global__ void pack_fused(PackJobs P)
{
    int blk = blockIdx.x, jb = 0;
#pragma unroll
    for (int t = 1; t < 7; ++t) if (blk >= P.start[t]) jb = t;
    long i = ((long)(blk - P.start[jb]) * 256 + threadIdx.x) * 4;
    float4 v = *reinterpret_cast<const float4*>(P.src[jb] + i);
    bf h0 = __float2bfloat16(v.x), h1 = __float2bfloat16(v.y);
    bf h2 = __float2bfloat16(v.z), h3 = __float2bfloat16(v.w);
    bf l0 = __float2bfloat16(v.x - __bfloat162float(h0));
    bf l1 = __float2bfloat16(v.y - __bfloat162float(h1));
    bf l2 = __float2bfloat16(v.z - __bfloat162float(h2));
    bf l3 = __float2bfloat16(v.w - __bfloat162float(h3));
    __nv_bfloat162 hp0(h0, h1), hp1(h2, h3), lp0(l0, l1), lp1(l2, l3);
    *reinterpret_cast<uint2*>(P.hi[jb] + i) = make_uint2(*(uint32_t*)&hp0, *(uint32_t*)&hp1);
    *reinterpret_cast<uint2*>(P.lo[jb] + i) = make_uint2(*(uint32_t*)&lp0, *(uint32_t*)&lp1);
}

// ---------------- int8-pair packers ----------------
__global__ void qpackA(const float* __restrict__ s, long n, float invS,
                       s8* __restrict__ q1, s8* __restrict__ q2)
{
    long i = ((long)blockIdx.x * blockDim.x + threadIdx.x) * 4;
    if (i >= n) return;
    float4 v = *reinterpret_cast<const float4*>(s + i);
    s8 a1, a2, b1, b2, c1, c2, d1, d2;
    qsplit(v.x, invS, a1, a2); qsplit(v.y, invS, b1, b2);
    qsplit(v.z, invS, c1, c2); qsplit(v.w, invS, d1, d2);
    *reinterpret_cast<char4*>(q1 + i) = make_char4(a1, b1, c1, d1);
    *reinterpret_cast<char4*>(q2 + i) = make_char4(a2, b2, c2, d2);
}
// fp32 [Kr][N] -> pair-interleaved [Kr/2][N] uint16
__global__ void qpackB(const float* __restrict__ s, int Kr, int N, float invS,
                       s8* __restrict__ q1, s8* __restrict__ q2)
{
    int idx = blockIdx.x * blockDim.x + threadIdx.x;
    if (idx >= Kr * N) return;
    int k = idx / N, n = idx - k * N;
    s8 a1, a2;
    qsplit(s[idx], invS, a1, a2);
    long o = ((long)(k >> 1) * N + n) * 2 + (k & 1);
    q1[o] = a1; q2[o] = a2;
}

// ---------------- bf16x3 prologue GEMM (R7-proven core) ----------------
// EPI 0: Cf = acc (XR). EPI 3: quantize acc into pair-interleaved B.
template <int EPI, int BN>
__global__ __launch_bounds__(256, 1) void hgemm(
    const bf* __restrict__ Ah, const bf* __restrict__ Al, int lda,
    const bf* __restrict__ Bh, const bf* __restrict__ Bl, int ldb, int K,
    float* __restrict__ Cf, int ldc,
    s8* __restrict__ Q1, s8* __restrict__ Q2, int ldq, float invSB)
{
    constexpr int WN = BN / 4, NFR = WN / 8, NL = NFR / 2;
    constexpr uint32_t BST = BN + 8, A_BLK = 10240u;
    constexpr uint32_t B_BLK = 32u * BST * 2u, STAGE = 2u * A_BLK + 2u * B_BLK;
    constexpr int CPT = BN / 64, BROW = BN / 8;
    extern __shared__ unsigned char smdyn[];
    const uint32_t sbase = smem_u32(smdyn);
    const int tid = threadIdx.x;
    const int m0 = blockIdx.y * 128, n0 = blockIdx.x * BN;

    auto loadStage = [&](int s, int kt) {
        const uint32_t sa = sbase + (uint32_t)s * STAGE;
#pragma unroll
        for (int j = 0; j < 2; ++j) {
            int t = tid + j * 256, row = t >> 2, c = (t & 3) * 8;
            long go = (long)(m0 + row) * lda + kt + c;
            uint32_t so = sa + (uint32_t)(row * 40 + c) * 2u;
            cp16(so, Ah + go); cp16(so + A_BLK, Al + go);
        }
        const uint32_t sb = sa + 2u * A_BLK;
#pragma unroll
        for (int j = 0; j < CPT; ++j) {
            int t = tid + j * 256, row = t / BROW, c = (t % BROW) * 8;
            long go = (long)(kt + row) * ldb + n0 + c;
            uint32_t so = sb + (uint32_t)(row * BST + c) * 2u;
            cp16(so, Bh + go); cp16(so + B_BLK, Bl + go);
        }
        CP_COMMIT();
    };

    float acc[4][NFR][4];
#pragma unroll
    for (int i = 0; i < 4; ++i)
#pragma unroll
        for (int j = 0; j < NFR; ++j)
#pragma unroll
            for (int q = 0; q < 4; ++q) acc[i][j][q] = 0.0f;

    const int lane = tid & 31, warp = tid >> 5;
    const int wm = (warp >> 2) * 64, wn = (warp & 3) * WN;
    const int NC = K / 32;
    loadStage(0, 0); loadStage(1, 32);
    for (int c = 0; c < NC; ++c) {
        asm volatile("cp.async.wait_group 1;" ::: "memory");
        __syncthreads();
        if (c + 2 < NC) loadStage((c + 2) % 3, (c + 2) * 32);
        else CP_COMMIT();
        const uint32_t aB = sbase + (uint32_t)(c % 3) * STAGE;
        const uint32_t bB = aB + 2u * A_BLK;
#pragma unroll
        for (int ks = 0; ks < 32; ks += 16) {
            uint32_t a0[4][4], a1[4][4], bh[NL][4], bl[NL][4];
#pragma unroll
            for (int mi = 0; mi < 4; ++mi) {
                uint32_t ad = aB + (uint32_t)((wm + mi * 16 + (lane & 15)) * 40 + ks + (lane >> 4) * 8) * 2u;
                LDSMX4(a0[mi], ad);
            }
#pragma unroll
            for (int nj = 0; nj < NL; ++nj) {
                uint32_t bd = bB + (uint32_t)((ks + (lane & 15)) * BST + wn + nj * 16 + (lane >> 4) * 8) * 2u;
                LDSMX4T(bh[nj], bd);
            }
#pragma unroll
            for (int mi = 0; mi < 4; ++mi)
#pragma unroll
                for (int ni = 0; ni < NFR; ++ni)
                    MMA(acc[mi][ni], a0[mi], bh[ni >> 1][(ni & 1) * 2], bh[ni >> 1][(ni & 1) * 2 + 1]);
#pragma unroll
            for (int mi = 0; mi < 4; ++mi) {
                uint32_t ad = aB + A_BLK + (uint32_t)((wm + mi * 16 + (lane & 15)) * 40 + ks + (lane >> 4) * 8) * 2u;
                LDSMX4(a1[mi], ad);
            }
#pragma unroll
            for (int mi = 0; mi < 4; ++mi)
#pragma unroll
                for (int ni = 0; ni < NFR; ++ni)
                    MMA(acc[mi][ni], a1[mi], bh[ni >> 1][(ni & 1) * 2], bh[ni >> 1][(ni & 1) * 2 + 1]);
#pragma unroll
            for (int nj = 0; nj < NL; ++nj) {
                uint32_t bd = bB + B_BLK + (uint32_t)((ks + (lane & 15)) * BST + wn + nj * 16 + (lane >> 4) * 8) * 2u;
                LDSMX4T(bl[nj], bd);
            }
#pragma unroll
            for (int mi = 0; mi < 4; ++mi)
#pragma unroll
                for (int ni = 0; ni < NFR; ++ni)
                    MMA(acc[mi][ni], a0[mi], bl[ni >> 1][(ni & 1) * 2], bl[ni >> 1][(ni & 1) * 2 + 1]);
        }
    }
#pragma unroll
    for (int mi = 0; mi < 4; ++mi)
#pragma unroll
        for (int ni = 0; ni < NFR; ++ni) {
            int col = n0 + wn + ni * 8 + (lane & 3) * 2;
#pragma unroll
            for (int h = 0; h < 2; ++h) {
                int row = m0 + wm + mi * 16 + (lane >> 2) + h * 8;
                float vx = acc[mi][ni][h * 2], vy = acc[mi][ni][h * 2 + 1];
                if (EPI == 0) {
                    *reinterpret_cast<float2*>(Cf + (long)row * ldc + col) = make_float2(vx, vy);
                } else {
                    s8 x1, x2, y1, y2;
                    qsplit(vx, invSB, x1, x2); qsplit(vy, invSB, y1, y2);
                    long o = ((long)(row >> 1) * ldq + col) * 2 + (row & 1);
                    Q1[o] = x1; Q2[o] = x2; Q1[o + 2] = y1; Q2[o + 2] = y2;
                }
            }
        }
}

// ---------------- int8 iteration GEMM: CTA 128x128, 8 warps 2Mx4N ---------
// A smem stride = 48 bytes (16B-aligned for cp.async; 40 was the R11 fault).
constexpr uint32_t IA_BLK = 128u * 48u;          // 6144
constexpr uint32_t IB_BLK = 16u * 136u * 2u;     // 4352
constexpr uint32_t ISTAGE = 2u * IA_BLK + 2u * IB_BLK;
constexpr uint32_t ISMEM  = 3u * ISTAGE;

template <int EPI>
__global__ __launch_bounds__(256, 1) void igemm(
    const s8* __restrict__ A0q1, const s8* __restrict__ A0q2, int lda0,
    const s8* __restrict__ A1q1, const s8* __restrict__ A1q2, int lda1, int ksplit,
    const s8* __restrict__ Bq1, const s8* __restrict__ Bq2, int ldbN, int K,
    float* __restrict__ Cf, int ldc,
    const float* __restrict__ XRp,
    const bf* __restrict__ Hh, const bf* __restrict__ Hl,
    bf* __restrict__ Chh, bf* __restrict__ Cll,
    s8* __restrict__ Cq1, s8* __restrict__ Cq2,
    float F1, float F2, float invSA)
{
    extern __shared__ unsigned char smdyn[];
    const uint32_t sbase = smem_u32(smdyn);
    const int tid = threadIdx.x;
    const int m0 = blockIdx.y * 128, n0 = blockIdx.x * 128;

    auto loadStage = [&](int s, int kt) {
        const s8 *p1, *p2; int lda, kk;
        if (kt < ksplit) { p1 = A0q1; p2 = A0q2; lda = lda0; kk = kt; }
        else             { p1 = A1q1; p2 = A1q2; lda = lda1; kk = kt - ksplit; }
        const uint32_t sa = sbase + (uint32_t)s * ISTAGE;
        {
            int row = tid >> 1, c = (tid & 1) * 16;
            long go = (long)(m0 + row) * lda + kk + c;
            uint32_t so = sa + (uint32_t)(row * 48 + c);
            cp16(so, p1 + go); cp16(so + IA_BLK, p2 + go);
        }
        const uint32_t sb = sa + 2u * IA_BLK;
        {
            int row = tid >> 4, c = tid & 15;
            long go = ((long)((kt >> 1) + row) * ldbN + n0 + c * 8) * 2;
            uint32_t so = sb + (uint32_t)(row * 272 + c * 16);
            cp16(so, Bq1 + go); cp16(so + IB_BLK, Bq2 + go);
        }
        CP_COMMIT();
    };

    int acch[4][4][4], accm[4][4][4];
#pragma unroll
    for (int i = 0; i < 4; ++i)
#pragma unroll
        for (int j = 0; j < 4; ++j)
#pragma unroll
            for (int q = 0; q < 4; ++q) { acch[i][j][q] = 0; accm[i][j][q] = 0; }

    const int lane = tid & 31, warp = tid >> 5;
    const int wm = (warp >> 2) * 64, wn = (warp & 3) * 32;
    const int NC = K / 32;
    loadStage(0, 0); loadStage(1, 32);
    for (int c = 0; c < NC; ++c) {
        asm volatile("cp.async.wait_group 1;" ::: "memory");
        __syncthreads();
        if (c + 2 < NC) loadStage((c + 2) % 3, (c + 2) * 32);
        else CP_COMMIT();
        const uint32_t aB = sbase + (uint32_t)(c % 3) * ISTAGE;
        const uint32_t bB = aB + 2u * IA_BLK;
        uint32_t q1f[4][4], q2f[4][4], b1f[2][4], b2f[2][4];
#pragma unroll
        for (int mi = 0; mi < 4; ++mi) {
            uint32_t ad = aB + (uint32_t)((wm + mi * 16 + (lane & 15)) * 24 + (lane >> 4) * 8) * 2u;
            LDSMX4(q1f[mi], ad); LDSMX4(q2f[mi], ad + IA_BLK);
        }
#pragma unroll
        for (int nj = 0; nj < 2; ++nj) {
            uint32_t bd = bB + (uint32_t)((lane & 15) * 136 + wn + nj * 16 + (lane >> 4) * 8) * 2u;
            LDSMX4T(b1f[nj], bd); LDSMX4T(b2f[nj], bd + IB_BLK);
        }
#pragma unroll
        for (int mi = 0; mi < 4; ++mi)
#pragma unroll
            for (int ni = 0; ni < 4; ++ni) {
                uint32_t u0 = b1f[ni >> 1][(ni & 1) * 2], u1 = b1f[ni >> 1][(ni & 1) * 2 + 1];
                uint32_t w0 = b2f[ni >> 1][(ni & 1) * 2], w1 = b2f[ni >> 1][(ni & 1) * 2 + 1];
                MMAS8(acch[mi][ni], q1f[mi], u0, u1);
                MMAS8(accm[mi][ni], q2f[mi], u0, u1);
                MMAS8(accm[mi][ni], q1f[mi], w0, w1);
            }
    }
#pragma unroll
    for (int mi = 0; mi < 4; ++mi)
#pragma unroll
        for (int ni = 0; ni < 4; ++ni) {
            int col = n0 + wn + ni * 8 + (lane & 3) * 2;
#pragma unroll
            for (int h = 0; h < 2; ++h) {
                int row = m0 + wm + mi * 16 + (lane >> 2) + h * 8;
                long o = (long)row * ldc + col;
                float vx = F1 * __int2float_rn(acch[mi][ni][h * 2]) +
                           F2 * __int2float_rn(accm[mi][ni][h * 2]);
                float vy = F1 * __int2float_rn(acch[mi][ni][h * 2 + 1]) +
                           F2 * __int2float_rn(accm[mi][ni][h * 2 + 1]);
                __nv_bfloat162 hh = *reinterpret_cast<const __nv_bfloat162*>(Hh + o);
                __nv_bfloat162 ll = *reinterpret_cast<const __nv_bfloat162*>(Hl + o);
                float sx = __bfloat162float(hh.x) + __bfloat162float(ll.x);
                float sy = __bfloat162float(hh.y) + __bfloat162float(ll.y);
                if (EPI == 1) { vx += sx - XRp[o]; vy += sy - XRp[o + 1]; }
                float nx = sx - ALPHA_C * fminf(fmaxf(vx, -1.0f), 1.0f);
                float ny = sy - ALPHA_C * fminf(fmaxf(vy, -1.0f), 1.0f);
                if (Cf) *reinterpret_cast<float2*>(Cf + o) = make_float2(nx, ny);
                bf hx = __float2bfloat16(nx), hy = __float2bfloat16(ny);
                bf lx = __float2bfloat16(nx - __bfloat162float(hx));
                bf ly = __float2bfloat16(ny - __bfloat162float(hy));
                __nv_bfloat162 hp(hx, hy), lp(lx, ly);
                *reinterpret_cast<uint32_t*>(Chh + o) = *(uint32_t*)&hp;
                *reinterpret_cast<uint32_t*>(Cll + o) = *(uint32_t*)&lp;
                s8 x1, x2, y1, y2;
                qsplit(nx, invSA, x1, x2); qsplit(ny, invSA, y1, y2);
                *reinterpret_cast<char2*>(Cq1 + o) = make_char2(x1, y1);
                *reinterpret_cast<char2*>(Cq2 + o) = make_char2(x2, y2);
            }
        }
}

template <int BN>
constexpr uint32_t smemBytes() {
    return 3u * (2u * 10240u + 2u * (32u * (BN + 8u) * 2u));
}

} // namespace

extern "C" void kernel_launch(void* const* d_in, const int* in_sizes, int n_in,
                              void* d_out, int out_size)
{
    const float *x = nullptr, *W1 = nullptr, *W2 = nullptr, *h1 = nullptr, *h2 = nullptr;
    for (int i = 0; i < n_in; ++i) {
        switch (in_sizes[i]) {
            case 8388608: x  = (const float*)d_in[i]; break;
            case 262144:  W1 = (const float*)d_in[i]; break;
            case 65536:   W2 = (const float*)d_in[i]; break;
            case 4194304: h1 = (const float*)d_in[i]; break;
            case 2097152: h2 = (const float*)d_in[i]; break;
        }
    }
    float* out = (float*)d_out;
    unsigned char* pool;
    cudaGetSymbolAddress((void**)&pool, g_pool);
    size_t off = 0;
    auto grab = [&](size_t bytes) -> void* {
        void* p = pool + off;
        off = (off + bytes + 1023) & ~(size_t)1023;
        return p;
    };
    float* W1e   = (float*)grab(8388608);
    float* W1re  = (float*)grab(8388608);
    float* K1low = (float*)grab(2097152);   // -What2   [512,1024]
    float* K2top = (float*)grab(2097152);   // -What2r  [1024,512]
    float* XR    = (float*)grab(16777216);
    bf* xh    = (bf*)grab(16777216); bf* xl    = (bf*)grab(16777216);
    bf* W1eh  = (bf*)grab(4194304);  bf* W1el  = (bf*)grab(4194304);
    bf* W1rh  = (bf*)grab(4194304);  bf* W1rl  = (bf*)grab(4194304);
    bf* nW2h  = (bf*)grab(1048576);  bf* nW2l  = (bf*)grab(1048576);
    bf* nW2rh = (bf*)grab(1048576);  bf* nW2rl = (bf*)grab(1048576);
    bf* H1h[2] = {(bf*)grab(8388608), (bf*)grab(8388608)};
    bf* H1l[2] = {(bf*)grab(8388608), (bf*)grab(8388608)};
    bf* H2h[2] = {(bf*)grab(4194304), (bf*)grab(4194304)};
    bf* H2l[2] = {(bf*)grab(4194304), (bf*)grab(4194304)};
    s8* H1q1[2] = {(s8*)grab(4194304), (s8*)grab(4194304)};
    s8* H1q2[2] = {(s8*)grab(4194304), (s8*)grab(4194304)};
    s8* H2q1[2] = {(s8*)grab(2097152), (s8*)grab(2097152)};
    s8* H2q2[2] = {(s8*)grab(2097152), (s8*)grab(2097152)};
    s8* B1q1 = (s8*)grab(1572864); s8* B1q2 = (s8*)grab(1572864);
    s8* B2q1 = (s8*)grab(786432);  s8* B2q2 = (s8*)grab(786432);

    const float invSA  = 32512.0f / 0.25f;
    const float sA     = 0.25f / 32512.0f;
    const float invSB1 = 32512.0f / 0.5f,  sB1 = 0.5f / 32512.0f;
    const float invSB2 = 32512.0f / 0.25f, sB2 = 0.25f / 32512.0f;
    const float F1_1 = sA * sB1 * 65536.0f, F2_1 = sA * sB1 * 256.0f;
    const float F1_2 = sA * sB2 * 65536.0f, F2_2 = sA * sB2 * 256.0f;

    cudaFuncSetAttribute(hgemm<0, 256>, cudaFuncAttributeMaxDynamicSharedMemorySize, smemBytes<256>());
    cudaFuncSetAttribute(hgemm<3, 64>,  cudaFuncAttributeMaxDynamicSharedMemorySize, smemBytes<64>());
    cudaFuncSetAttribute(igemm<1>, cudaFuncAttributeMaxDynamicSharedMemorySize, ISMEM);
    cudaFuncSetAttribute(igemm<2>, cudaFuncAttributeMaxDynamicSharedMemorySize, ISMEM);

    ExpandJobs E;
    E.W[0] = W1; E.out[0] = W1e;   E.J[0] = 128; E.I[0] = 256; E.rev[0] = 0; E.sgn[0] =  1.0f;
    E.W[1] = W1; E.out[1] = W1re;  E.J[1] = 256; E.I[1] = 128; E.rev[1] = 1; E.sgn[1] =  1.0f;
    E.W[2] = W2; E.out[2] = K1low; E.J[2] = 64;  E.I[2] = 128; E.rev[2] = 0; E.sgn[2] = -1.0f;
    E.W[3] = W2; E.out[3] = K2top; E.J[3] = 128; E.I[3] = 64;  E.rev[3] = 1; E.sgn[3] = -1.0f;
    E.start[0] = 0; E.start[1] = 8192; E.start[2] = 16384; E.start[3] = 18432; E.start[4] = 20480;
    expand_fused<<<20480, 256>>>(E);

    PackJobs P;
    P.src[0] = x;     P.hi[0] = xh;    P.lo[0] = xl;
    P.src[1] = W1e;   P.hi[1] = W1eh;  P.lo[1] = W1el;
    P.src[2] = W1re;  P.hi[2] = W1rh;  P.lo[2] = W1rl;
    P.src[3] = h1;    P.hi[3] = H1h[0]; P.lo[3] = H1l[0];
    P.src[4] = h2;    P.hi[4] = H2h[0]; P.lo[4] = H2l[0];
    P.src[5] = K1low; P.hi[5] = nW2h;  P.lo[5] = nW2l;
    P.src[6] = K2top; P.hi[6] = nW2rh; P.lo[6] = nW2rl;
    P.start[0] = 0;     P.start[1] = 8192;  P.start[2] = 10240; P.start[3] = 12288;
    P.start[4] = 16384; P.start[5] = 18432; P.start[6] = 18944; P.start[7] = 19456;
    pack_fused<<<19456, 256>>>(P);

    qpackA<<<4096, 256>>>(h1, 4194304, invSA, H1q1[0], H1q2[0]);
    qpackA<<<2048, 256>>>(h2, 2097152, invSA, H2q1[0], H2q2[0]);
    qpackB<<<2048, 256>>>(K1low, 512, 1024, invSB1, B1q1 + 512 * 1024 * 2, B1q2 + 512 * 1024 * 2);
    qpackB<<<2048, 256>>>(K2top, 1024, 512, invSB2, B2q1, B2q2);

    // XR = x @ What1r  [4096,1024], K=2048
    hgemm<0, 256><<<dim3(4, 32), 256, smemBytes<256>()>>>(
        xh, xl, 2048, W1rh, W1rl, 1024, 2048, XR, 1024, nullptr, nullptr, 0, 0.0f);
    // M1 (no +I; folded into igemm epilogue) -> B1 rows 0..1023  [1024,1024], K=2048
    hgemm<3, 64><<<dim3(16, 8), 256, smemBytes<64>()>>>(
        W1eh, W1el, 2048, W1rh, W1rl, 1024, 2048, nullptr, 0, B1q1, B1q2, 1024, invSB1);
    // M2 = (-W2)@(-W2r) -> B2 rows 1024..1535  [512,512], K=1024
    hgemm<3, 64><<<dim3(8, 4), 256, smemBytes<64>()>>>(
        nW2h, nW2l, 1024, nW2rh, nW2rl, 512, 1024, nullptr, 0,
        B2q1 + 512 * 512 * 2, B2q2 + 512 * 512 * 2, 512, invSB2);

    cudaMemcpyAsync(out, x, 33554432, cudaMemcpyDeviceToDevice, 0);
    float* out_h1 = out + 8388608;
    float* out_h2 = out + 12582912;

    for (int it = 0; it < 20; ++it) {
        int rd = it & 1, wr = 1 - rd;
        bool last = (it == 19);
        // H1' = H1 - a*clip([H1|H2]@K1' + H1 - XR)   [4096,1024], K=1536
        igemm<1><<<dim3(8, 32), 256, ISMEM>>>(
            H1q1[rd], H1q2[rd], 1024, H2q1[rd], H2q2[rd], 512, 1024,
            B1q1, B1q2, 1024, 1536, last ? out_h1 : nullptr, 1024,
            XR, H1h[rd], H1l[rd], H1h[wr], H1l[wr], H1q1[wr], H1q2[wr],
            F1_1, F2_1, invSA);
        // H2' = H2 - a*clip([H1'|H2]@K2)             [4096,512], K=1536
        igemm<2><<<dim3(4, 32), 256, ISMEM>>>(
            H1q1[wr], H1q2[wr], 1024, H2q1[rd], H2q2[rd], 512, 1024,
            B2q1, B2q2, 512, 1536, last ? out_h2 : nullptr, 512,
            nullptr, H2h[rd], H2l[rd], H2h[wr], H2l[wr], H2q1[wr], H2q2[wr],
            F1_2, F2_2, invSA);
    }
}

// round 13
// speedup vs baseline: 2.5239x; 2.5239x over previous
#include <cuda_runtime.h>
#include <cuda_bf16.h>
#include <cstdint>

namespace {

constexpr float ALPHA_C = 0.01f;
typedef __nv_bfloat16 bf;

__device__ __align__(1024) unsigned char g_pool[200u * 1024u * 1024u];

__device__ __forceinline__ uint32_t smem_u32(const void* p) {
    uint32_t a;
    asm("{ .reg .u64 t; cvta.to.shared.u64 t, %1; cvt.u32.u64 %0, t; }" : "=r"(a) : "l"(p));
    return a;
}
__device__ __forceinline__ void cp16(uint32_t s, const void* g) {
    asm volatile("cp.async.cg.shared.global [%0], [%1], 16;" :: "r"(s), "l"(g) : "memory");
}
#define CP_COMMIT() asm volatile("cp.async.commit_group;" ::: "memory")
#define LDSMX4(r, addr) \
    asm volatile("ldmatrix.sync.aligned.m8n8.x4.shared.b16 {%0,%1,%2,%3}, [%4];" \
        : "=r"((r)[0]), "=r"((r)[1]), "=r"((r)[2]), "=r"((r)[3]) : "r"(addr))
#define LDSMX4T(r, addr) \
    asm volatile("ldmatrix.sync.aligned.m8n8.x4.trans.shared.b16 {%0,%1,%2,%3}, [%4];" \
        : "=r"((r)[0]), "=r"((r)[1]), "=r"((r)[2]), "=r"((r)[3]) : "r"(addr))
#define MMA(c, a, b0, b1) \
    asm volatile("mma.sync.aligned.m16n8k16.row.col.f32.bf16.bf16.f32 " \
        "{%0,%1,%2,%3}, {%4,%5,%6,%7}, {%8,%9}, {%0,%1,%2,%3};" \
        : "+f"((c)[0]), "+f"((c)[1]), "+f"((c)[2]), "+f"((c)[3]) \
        : "r"((a)[0]), "r"((a)[1]), "r"((a)[2]), "r"((a)[3]), "r"(b0), "r"(b1))

// ---------------- fused Cayley expansion (validated) ----------------
struct ExpandJobs {
    const float* W[4]; float* out[4];
    int J[4], I[4], rev[4]; float sgn[4]; int start[5];
};
__device__ __forceinline__ int reorder_sign(int a, int b) {
    int s = 0; int aa = a >> 1;
    while (aa) { s += __popc(aa & b); aa >>= 1; }
    return (s & 1) ? -1 : 1;
}
__global__ void expand_fused(ExpandJobs E)
{
    int blk = blockIdx.x, jb = 0;
#pragma unroll
    for (int t = 1; t < 4; ++t) if (blk >= E.start[t]) jb = t;
    int J = E.J[jb], I = E.I[jb];
    int idx = (blk - E.start[jb]) * 256 + threadIdx.x;
    int ncol = I * 8;
    int col = idx % ncol, row = idx / ncol;
    int a = row & 7, j = row >> 3, c = col & 7, i = col >> 3, e = a ^ c;
    float s = (float)reorder_sign(a, e) * E.sgn[jb];
    size_t widx;
    if (E.rev[jb]) {
        int k = __popc(e);
        if ((k * (k - 1) / 2) & 1) s = -s;
        widx = (size_t)j * ncol + (size_t)i * 8 + e;
    } else {
        widx = (size_t)i * (size_t)(J * 8) + (size_t)j * 8 + e;
    }
    E.out[jb][idx] = s * E.W[jb][widx];
}

// ---------------- fused fp32 -> bf16 hi/lo packer ----------------
struct PackJobs {
    const float* src[7]; bf* hi[7]; bf* lo[7]; int start[8];
};
__global__ void pack_fused(PackJobs P)
{
    int blk = blockIdx.x, jb = 0;
#pragma unroll
    for (int t = 1; t < 7; ++t) if (blk >= P.start[t]) jb = t;
    long i = ((long)(blk - P.start[jb]) * 256 + threadIdx.x) * 4;
    float4 v = *reinterpret_cast<const float4*>(P.src[jb] + i);
    bf h0 = __float2bfloat16(v.x), h1 = __float2bfloat16(v.y);
    bf h2 = __float2bfloat16(v.z), h3 = __float2bfloat16(v.w);
    bf l0 = __float2bfloat16(v.x - __bfloat162float(h0));
    bf l1 = __float2bfloat16(v.y - __bfloat162float(h1));
    bf l2 = __float2bfloat16(v.z - __bfloat162float(h2));
    bf l3 = __float2bfloat16(v.w - __bfloat162float(h3));
    __nv_bfloat162 hp0(h0, h1), hp1(h2, h3), lp0(l0, l1), lp1(l2, l3);
    *reinterpret_cast<uint2*>(P.hi[jb] + i) = make_uint2(*(uint32_t*)&hp0, *(uint32_t*)&hp1);
    *reinterpret_cast<uint2*>(P.lo[jb] + i) = make_uint2(*(uint32_t*)&lp0, *(uint32_t*)&lp1);
}

// ---------------------------------------------------------------------------
// bf16x3 mma.sync GEMM: C[m,n] = sum_k A[m,k]*B[k,n], A=[A0|A1] along K.
// 512 threads = 16 warps in a 4M x 4N grid; warp tile 32 x (BN/4).
// (R10's regression came from the 2Mx8N grid: 8-way A redundancy. 4x4 keeps
//  LDSM bytes/MMA at ~128 while doubling warps/SMSP vs the 8-warp R7 config.)
// 3-stage cp.async, one __syncthreads per 32-k chunk.
// EPI 0: Cf = acc                                        (XR)
// EPI 1: g=clip(acc-XR); v=(Hh+Hl)-a*g; [Cf],[Ch/Cl]     (H1 update)
// EPI 2: g=clip(acc);    v=(Hh+Hl)-a*g; [Cf],[Ch/Cl]     (H2 update)
// EPI 3: v=acc(+I if addI); Ch/Cl                        (M1/M2 weights)
// ---------------------------------------------------------------------------
template <int EPI, int BN>
__global__ __launch_bounds__(512, 1) void hgemm(
    const bf* __restrict__ A0h, const bf* __restrict__ A0l, int lda0,
    const bf* __restrict__ A1h, const bf* __restrict__ A1l, int lda1, int ksplit,
    const bf* __restrict__ Bh, const bf* __restrict__ Bl, int ldb, int K,
    float* __restrict__ Cf, int ldc,
    const float* __restrict__ XRp,
    const bf* __restrict__ Hh, const bf* __restrict__ Hl,
    bf* __restrict__ Ch, bf* __restrict__ Cl, int addI)
{
    constexpr int WN  = BN / 4;
    constexpr int NFR = WN / 8;
    constexpr int NL  = NFR / 2;
    constexpr uint32_t BST   = BN + 8;
    constexpr uint32_t A_BLK = 10240u;
    constexpr uint32_t B_BLK = 32u * BST * 2u;
    constexpr uint32_t STAGE = 2u * A_BLK + 2u * B_BLK;
    constexpr int BTOT = 4 * BN;          // B cp16 transfers per operand

    extern __shared__ unsigned char smdyn[];
    const uint32_t sbase = smem_u32(smdyn);
    const int tid = threadIdx.x;
    const int m0 = blockIdx.y * 128, n0 = blockIdx.x * BN;

    auto loadStage = [&](int s, int kt) {
        const bf *Ah, *Al;
        int lda, kk;
        if (kt < ksplit) { Ah = A0h; Al = A0l; lda = lda0; kk = kt; }
        else             { Ah = A1h; Al = A1l; lda = lda1; kk = kt - ksplit; }
        const uint32_t sa = sbase + (uint32_t)s * STAGE;
        {
            int row = tid >> 2, c = (tid & 3) * 8;       // 512 cp16 = full A chunk
            long go = (long)(m0 + row) * lda + kk + c;
            uint32_t so = sa + (uint32_t)(row * 40 + c) * 2u;
            cp16(so, Ah + go); cp16(so + A_BLK, Al + go);
        }
        const uint32_t sb = sa + 2u * A_BLK;
#pragma unroll
        for (int j = 0; j < (BTOT + 511) / 512; ++j) {
            int t = tid + j * 512;
            if ((BTOT % 512 == 0) || t < BTOT) {
                int row = t / (BN / 8), c = (t % (BN / 8)) * 8;
                long go = (long)(kt + row) * ldb + n0 + c;
                uint32_t so = sb + (uint32_t)(row * BST + c) * 2u;
                cp16(so, Bh + go); cp16(so + B_BLK, Bl + go);
            }
        }
        CP_COMMIT();
    };

    float acc[2][NFR][4];
#pragma unroll
    for (int i = 0; i < 2; ++i)
#pragma unroll
        for (int j = 0; j < NFR; ++j)
#pragma unroll
            for (int q = 0; q < 4; ++q) acc[i][j][q] = 0.0f;

    const int lane = tid & 31, warp = tid >> 5;
    const int wm = (warp >> 2) * 32, wn = (warp & 3) * WN;
    const int NC = K / 32;

    loadStage(0, 0);
    loadStage(1, 32);

    for (int c = 0; c < NC; ++c) {
        asm volatile("cp.async.wait_group 1;" ::: "memory");
        __syncthreads();
        if (c + 2 < NC) loadStage((c + 2) % 3, (c + 2) * 32);
        else CP_COMMIT();

        const uint32_t aB = sbase + (uint32_t)(c % 3) * STAGE;
        const uint32_t bB = aB + 2u * A_BLK;
#pragma unroll
        for (int ks = 0; ks < 32; ks += 16) {
            uint32_t a0[2][4], a1[2][4], bh[NL][4], bl[NL][4];
#pragma unroll
            for (int mi = 0; mi < 2; ++mi) {
                uint32_t ad = aB + (uint32_t)((wm + mi * 16 + (lane & 15)) * 40 + ks + (lane >> 4) * 8) * 2u;
                LDSMX4(a0[mi], ad);
                LDSMX4(a1[mi], ad + A_BLK);
            }
#pragma unroll
            for (int nj = 0; nj < NL; ++nj) {
                uint32_t bd = bB + (uint32_t)((ks + (lane & 15)) * BST + wn + nj * 16 + (lane >> 4) * 8) * 2u;
                LDSMX4T(bh[nj], bd);
            }
#pragma unroll
            for (int mi = 0; mi < 2; ++mi)
#pragma unroll
                for (int ni = 0; ni < NFR; ++ni)
                    MMA(acc[mi][ni], a0[mi], bh[ni >> 1][(ni & 1) * 2], bh[ni >> 1][(ni & 1) * 2 + 1]);
#pragma unroll
            for (int mi = 0; mi < 2; ++mi)
#pragma unroll
                for (int ni = 0; ni < NFR; ++ni)
                    MMA(acc[mi][ni], a1[mi], bh[ni >> 1][(ni & 1) * 2], bh[ni >> 1][(ni & 1) * 2 + 1]);
#pragma unroll
            for (int nj = 0; nj < NL; ++nj) {
                uint32_t bd = bB + B_BLK + (uint32_t)((ks + (lane & 15)) * BST + wn + nj * 16 + (lane >> 4) * 8) * 2u;
                LDSMX4T(bl[nj], bd);
            }
#pragma unroll
            for (int mi = 0; mi < 2; ++mi)
#pragma unroll
                for (int ni = 0; ni < NFR; ++ni)
                    MMA(acc[mi][ni], a0[mi], bl[ni >> 1][(ni & 1) * 2], bl[ni >> 1][(ni & 1) * 2 + 1]);
        }
    }

    // ---- fused epilogue ----
#pragma unroll
    for (int mi = 0; mi < 2; ++mi)
#pragma unroll
        for (int ni = 0; ni < NFR; ++ni) {
            int col = n0 + wn + ni * 8 + (lane & 3) * 2;
#pragma unroll
            for (int h = 0; h < 2; ++h) {
                int row = m0 + wm + mi * 16 + (lane >> 2) + h * 8;
                float vx = acc[mi][ni][h * 2], vy = acc[mi][ni][h * 2 + 1];
                long o = (long)row * ldc + col;
                if (EPI == 1) { vx -= XRp[o]; vy -= XRp[o + 1]; }
                if (EPI == 1 || EPI == 2) {
                    vx = fminf(fmaxf(vx, -1.0f), 1.0f);
                    vy = fminf(fmaxf(vy, -1.0f), 1.0f);
                    __nv_bfloat162 hh = *reinterpret_cast<const __nv_bfloat162*>(Hh + o);
                    __nv_bfloat162 ll = *reinterpret_cast<const __nv_bfloat162*>(Hl + o);
                    vx = (__bfloat162float(hh.x) + __bfloat162float(ll.x)) - ALPHA_C * vx;
                    vy = (__bfloat162float(hh.y) + __bfloat162float(ll.y)) - ALPHA_C * vy;
                }
                if (EPI == 3 && addI) {
                    if (row == col)     vx += 1.0f;
                    if (row == col + 1) vy += 1.0f;
                }
                if (EPI == 0 || ((EPI == 1 || EPI == 2) && Cf))
                    *reinterpret_cast<float2*>(Cf + o) = make_float2(vx, vy);
                if (EPI == 3 || ((EPI == 1 || EPI == 2) && Ch)) {
                    bf hx = __float2bfloat16(vx), hy = __float2bfloat16(vy);
                    bf lx = __float2bfloat16(vx - __bfloat162float(hx));
                    bf ly = __float2bfloat16(vy - __bfloat162float(hy));
                    __nv_bfloat162 hp(hx, hy), lp(lx, ly);
                    *reinterpret_cast<uint32_t*>(Ch + o) = *(uint32_t*)&hp;
                    *reinterpret_cast<uint32_t*>(Cl + o) = *(uint32_t*)&lp;
                }
            }
        }
}

template <int BN>
constexpr uint32_t smemBytes() {
    return 3u * (2u * 10240u + 2u * (32u * (BN + 8u) * 2u));
}

} // namespace

extern "C" void kernel_launch(void* const* d_in, const int* in_sizes, int n_in,
                              void* d_out, int out_size)
{
    const float *x = nullptr, *W1 = nullptr, *W2 = nullptr, *h1 = nullptr, *h2 = nullptr;
    for (int i = 0; i < n_in; ++i) {
        switch (in_sizes[i]) {
            case 8388608: x  = (const float*)d_in[i]; break;
            case 262144:  W1 = (const float*)d_in[i]; break;
            case 65536:   W2 = (const float*)d_in[i]; break;
            case 4194304: h1 = (const float*)d_in[i]; break;
            case 2097152: h2 = (const float*)d_in[i]; break;
        }
    }
    float* out = (float*)d_out;

    unsigned char* pool;
    cudaGetSymbolAddress((void**)&pool, g_pool);
    size_t off = 0;
    auto grab = [&](size_t bytes) -> void* {
        void* p = pool + off;
        off = (off + bytes + 1023) & ~(size_t)1023;
        return p;
    };
    float* W1e   = (float*)grab(8388608);
    float* W1re  = (float*)grab(8388608);
    float* K1low = (float*)grab(2097152);
    float* K2top = (float*)grab(2097152);
    float* XR    = (float*)grab(16777216);
    bf* xh   = (bf*)grab(16777216); bf* xl   = (bf*)grab(16777216);
    bf* W1eh = (bf*)grab(4194304);  bf* W1el = (bf*)grab(4194304);
    bf* W1rh = (bf*)grab(4194304);  bf* W1rl = (bf*)grab(4194304);
    bf* H1h[2] = {(bf*)grab(8388608), (bf*)grab(8388608)};
    bf* H1l[2] = {(bf*)grab(8388608), (bf*)grab(8388608)};
    bf* H2h[2] = {(bf*)grab(4194304), (bf*)grab(4194304)};
    bf* H2l[2] = {(bf*)grab(4194304), (bf*)grab(4194304)};
    bf* K1h = (bf*)grab(3145728);  bf* K1l = (bf*)grab(3145728);
    bf* K2h = (bf*)grab(1572864);  bf* K2l = (bf*)grab(1572864);

    cudaFuncSetAttribute(hgemm<0, 256>, cudaFuncAttributeMaxDynamicSharedMemorySize, smemBytes<256>());
    cudaFuncSetAttribute(hgemm<1, 256>, cudaFuncAttributeMaxDynamicSharedMemorySize, smemBytes<256>());
    cudaFuncSetAttribute(hgemm<2, 128>, cudaFuncAttributeMaxDynamicSharedMemorySize, smemBytes<128>());
    cudaFuncSetAttribute(hgemm<3, 64>,  cudaFuncAttributeMaxDynamicSharedMemorySize, smemBytes<64>());

    const int NOSPLIT = 0x40000000;

    ExpandJobs E;
    E.W[0] = W1; E.out[0] = W1e;   E.J[0] = 128; E.I[0] = 256; E.rev[0] = 0; E.sgn[0] =  1.0f;
    E.W[1] = W1; E.out[1] = W1re;  E.J[1] = 256; E.I[1] = 128; E.rev[1] = 1; E.sgn[1] =  1.0f;
    E.W[2] = W2; E.out[2] = K1low; E.J[2] = 64;  E.I[2] = 128; E.rev[2] = 0; E.sgn[2] = -1.0f;
    E.W[3] = W2; E.out[3] = K2top; E.J[3] = 128; E.I[3] = 64;  E.rev[3] = 1; E.sgn[3] = -1.0f;
    E.start[0] = 0; E.start[1] = 8192; E.start[2] = 16384; E.start[3] = 18432; E.start[4] = 20480;
    expand_fused<<<20480, 256>>>(E);

    PackJobs P;
    P.src[0] = x;     P.hi[0] = xh;                 P.lo[0] = xl;
    P.src[1] = W1e;   P.hi[1] = W1eh;               P.lo[1] = W1el;
    P.src[2] = W1re;  P.hi[2] = W1rh;               P.lo[2] = W1rl;
    P.src[3] = h1;    P.hi[3] = H1h[0];             P.lo[3] = H1l[0];
    P.src[4] = h2;    P.hi[4] = H2h[0];             P.lo[4] = H2l[0];
    P.src[5] = K1low; P.hi[5] = K1h + 1024 * 1024;  P.lo[5] = K1l + 1024 * 1024;
    P.src[6] = K2top; P.hi[6] = K2h;                P.lo[6] = K2l;
    P.start[0] = 0;     P.start[1] = 8192;  P.start[2] = 10240; P.start[3] = 12288;
    P.start[4] = 16384; P.start[5] = 18432; P.start[6] = 18944; P.start[7] = 19456;
    pack_fused<<<19456, 256>>>(P);

    // XR = x @ What1r  [4096,1024], K=2048
    hgemm<0, 256><<<dim3(4, 32), 512, smemBytes<256>()>>>(
        xh, xl, 2048, nullptr, nullptr, 0, NOSPLIT,
        W1rh, W1rl, 1024, 2048, XR, 1024, nullptr, nullptr, nullptr, nullptr, nullptr, 0);
    // K1 top = What1@What1r + I  [1024,1024], K=2048
    hgemm<3, 64><<<dim3(16, 8), 512, smemBytes<64>()>>>(
        W1eh, W1el, 2048, nullptr, nullptr, 0, NOSPLIT,
        W1rh, W1rl, 1024, 2048, nullptr, 1024, nullptr, nullptr, nullptr, K1h, K1l, 1);
    // K2 bottom = (-What2)@(-What2r)  [512,512], K=1024
    hgemm<3, 64><<<dim3(8, 4), 512, smemBytes<64>()>>>(
        K1h + 1024 * 1024, K1l + 1024 * 1024, 1024, nullptr, nullptr, 0, NOSPLIT,
        K2h, K2l, 512, 1024, nullptr, 512, nullptr, nullptr, nullptr,
        K2h + 1024 * 512, K2l + 1024 * 512, 0);

    cudaMemcpyAsync(out, x, 33554432, cudaMemcpyDeviceToDevice, 0);
    float* out_h1 = out + 8388608;
    float* out_h2 = out + 12582912;

    for (int it = 0; it < 20; ++it) {
        int rd = it & 1, wr = 1 - rd;
        bool last = (it == 19);
        float* c1 = last ? out_h1 : nullptr;
        float* c2 = last ? out_h2 : nullptr;
        bf* p1h = H1h[wr]; bf* p1l = H1l[wr];
        bf* p2h = last ? nullptr : H2h[wr];
        bf* p2l = last ? nullptr : H2l[wr];
        // H1' = H1 - a*clip([H1|H2]@K1 - XR)   [4096,1024], K=1536
        hgemm<1, 256><<<dim3(4, 32), 512, smemBytes<256>()>>>(
            H1h[rd], H1l[rd], 1024, H2h[rd], H2l[rd], 512, 1024,
            K1h, K1l, 1024, 1536, c1, 1024, XR, H1h[rd], H1l[rd], p1h, p1l, 0);
        // H2' = H2 - a*clip([H1'|H2]@K2)       [4096,512], K=1536
        hgemm<2, 128><<<dim3(4, 32), 512, smemBytes<128>()>>>(
            H1h[wr], H1l[wr], 1024, H2h[rd], H2l[rd], 512, 1024,
            K2h, K2l, 512, 1536, c2, 512, nullptr, H2h[rd], H2l[rd], p2h, p2l, 0);
    }
}

// round 14
// speedup vs baseline: 2.5389x; 1.0059x over previous
#include <cuda_runtime.h>
#include <cuda_fp16.h>
#include <cstdint>

namespace {

constexpr float ALPHA_C = 0.01f;
typedef __half hf;

__device__ __align__(1024) unsigned char g_pool[200u * 1024u * 1024u];

__device__ __forceinline__ uint32_t smem_u32(const void* p) {
    uint32_t a;
    asm("{ .reg .u64 t; cvta.to.shared.u64 t, %1; cvt.u32.u64 %0, t; }" : "=r"(a) : "l"(p));
    return a;
}
__device__ __forceinline__ void cp16(uint32_t s, const void* g) {
    asm volatile("cp.async.cg.shared.global [%0], [%1], 16;" :: "r"(s), "l"(g) : "memory");
}
#define CP_COMMIT() asm volatile("cp.async.commit_group;" ::: "memory")
#define LDSMX4(r, addr) \
    asm volatile("ldmatrix.sync.aligned.m8n8.x4.shared.b16 {%0,%1,%2,%3}, [%4];" \
        : "=r"((r)[0]), "=r"((r)[1]), "=r"((r)[2]), "=r"((r)[3]) : "r"(addr))
#define LDSMX4T(r, addr) \
    asm volatile("ldmatrix.sync.aligned.m8n8.x4.trans.shared.b16 {%0,%1,%2,%3}, [%4];" \
        : "=r"((r)[0]), "=r"((r)[1]), "=r"((r)[2]), "=r"((r)[3]) : "r"(addr))
#define MMA(c, a, b0, b1) \
    asm volatile("mma.sync.aligned.m16n8k16.row.col.f32.f16.f16.f32 " \
        "{%0,%1,%2,%3}, {%4,%5,%6,%7}, {%8,%9}, {%0,%1,%2,%3};" \
        : "+f"((c)[0]), "+f"((c)[1]), "+f"((c)[2]), "+f"((c)[3]) \
        : "r"((a)[0]), "r"((a)[1]), "r"((a)[2]), "r"((a)[3]), "r"(b0), "r"(b1))

__device__ __forceinline__ void hsplit(float v, hf& h, hf& l) {
    h = __float2half_rn(v);
    l = __float2half_rn(v - __half2float(h));
}
__device__ __forceinline__ uint32_t packh2(hf a, hf b) {
    __half2 p = __halves2half2(a, b);
    return *reinterpret_cast<uint32_t*>(&p);
}

// ---------------- fused Cayley expansion (validated) ----------------
struct ExpandJobs {
    const float* W[4]; float* out[4];
    int J[4], I[4], rev[4]; float sgn[4]; int start[5];
};
__device__ __forceinline__ int reorder_sign(int a, int b) {
    int s = 0; int aa = a >> 1;
    while (aa) { s += __popc(aa & b); aa >>= 1; }
    return (s & 1) ? -1 : 1;
}
__global__ void expand_fused(ExpandJobs E)
{
    int blk = blockIdx.x, jb = 0;
#pragma unroll
    for (int t = 1; t < 4; ++t) if (blk >= E.start[t]) jb = t;
    int J = E.J[jb], I = E.I[jb];
    int idx = (blk - E.start[jb]) * 256 + threadIdx.x;
    int ncol = I * 8;
    int col = idx % ncol, row = idx / ncol;
    int a = row & 7, j = row >> 3, c = col & 7, i = col >> 3, e = a ^ c;
    float s = (float)reorder_sign(a, e) * E.sgn[jb];
    size_t widx;
    if (E.rev[jb]) {
        int k = __popc(e);
        if ((k * (k - 1) / 2) & 1) s = -s;
        widx = (size_t)j * ncol + (size_t)i * 8 + e;
    } else {
        widx = (size_t)i * (size_t)(J * 8) + (size_t)j * 8 + e;
    }
    E.out[jb][idx] = s * E.W[jb][widx];
}

// ---------------- fused fp32 -> fp16 hi/lo packer ----------------
struct PackJobs {
    const float* src[7]; hf* hi[7]; hf* lo[7]; int start[8];
};
__global__ void pack_fused(PackJobs P)
{
    int blk = blockIdx.x, jb = 0;
#pragma unroll
    for (int t = 1; t < 7; ++t) if (blk >= P.start[t]) jb = t;
    long i = ((long)(blk - P.start[jb]) * 256 + threadIdx.x) * 4;
    float4 v = *reinterpret_cast<const float4*>(P.src[jb] + i);
    hf h0, l0, h1, l1, h2, l2, h3, l3;
    hsplit(v.x, h0, l0); hsplit(v.y, h1, l1);
    hsplit(v.z, h2, l2); hsplit(v.w, h3, l3);
    *reinterpret_cast<uint2*>(P.hi[jb] + i) = make_uint2(packh2(h0, h1), packh2(h2, h3));
    *reinterpret_cast<uint2*>(P.lo[jb] + i) = make_uint2(packh2(l0, l1), packh2(l2, l3));
}

// ---------------------------------------------------------------------------
// fp16x3 mma.sync GEMM: C[m,n] = sum_k A[m,k]*B[k,n], A=[A0|A1] along K.
// Exact R7-best structure: CTA 128 x BN, 8 warps (2M x 4N) of 64 x BN/4,
// 3-stage cp.async, one __syncthreads per 32-k chunk. Only the MMA dtype and
// the pair representation changed (bf16 -> fp16) to test the HMMA f16 rate.
// EPI 0: Cf = acc                                        (XR)
// EPI 1: g=clip(acc-XR); v=(Hh+Hl)-a*g; [Cf],[Ch/Cl]     (H1 update)
// EPI 2: g=clip(acc);    v=(Hh+Hl)-a*g; [Cf],[Ch/Cl]     (H2 update)
// EPI 3: v=acc(+I if addI); Ch/Cl                        (M1/M2 weights)
// ---------------------------------------------------------------------------
template <int EPI, int BN>
__global__ __launch_bounds__(256, 1) void hgemm(
    const hf* __restrict__ A0h, const hf* __restrict__ A0l, int lda0,
    const hf* __restrict__ A1h, const hf* __restrict__ A1l, int lda1, int ksplit,
    const hf* __restrict__ Bh, const hf* __restrict__ Bl, int ldb, int K,
    float* __restrict__ Cf, int ldc,
    const float* __restrict__ XRp,
    const hf* __restrict__ Hh, const hf* __restrict__ Hl,
    hf* __restrict__ Ch, hf* __restrict__ Cl, int addI)
{
    constexpr int WN  = BN / 4;
    constexpr int NFR = WN / 8;
    constexpr int NL  = NFR / 2;
    constexpr uint32_t BST   = BN + 8;
    constexpr uint32_t A_BLK = 10240u;
    constexpr uint32_t B_BLK = 32u * BST * 2u;
    constexpr uint32_t STAGE = 2u * A_BLK + 2u * B_BLK;
    constexpr int CPT = BN / 64;
    constexpr int BROW = BN / 8;

    extern __shared__ unsigned char smdyn[];
    const uint32_t sbase = smem_u32(smdyn);
    const int tid = threadIdx.x;
    const int m0 = blockIdx.y * 128, n0 = blockIdx.x * BN;

    auto loadStage = [&](int s, int kt) {
        const hf *Ah, *Al;
        int lda, kk;
        if (kt < ksplit) { Ah = A0h; Al = A0l; lda = lda0; kk = kt; }
        else             { Ah = A1h; Al = A1l; lda = lda1; kk = kt - ksplit; }
        const uint32_t sa = sbase + (uint32_t)s * STAGE;
#pragma unroll
        for (int j = 0; j < 2; ++j) {
            int t = tid + j * 256;
            int row = t >> 2, c = (t & 3) * 8;
            long go = (long)(m0 + row) * lda + kk + c;
            uint32_t so = sa + (uint32_t)(row * 40 + c) * 2u;
            cp16(so, Ah + go);
            cp16(so + A_BLK, Al + go);
        }
        const uint32_t sb = sa + 2u * A_BLK;
#pragma unroll
        for (int j = 0; j < CPT; ++j) {
            int t = tid + j * 256;
            int row = t / BROW, c = (t % BROW) * 8;
            long go = (long)(kt + row) * ldb + n0 + c;
            uint32_t so = sb + (uint32_t)(row * BST + c) * 2u;
            cp16(so, Bh + go);
            cp16(so + B_BLK, Bl + go);
        }
        CP_COMMIT();
    };

    float acc[4][NFR][4];
#pragma unroll
    for (int i = 0; i < 4; ++i)
#pragma unroll
        for (int j = 0; j < NFR; ++j)
#pragma unroll
            for (int q = 0; q < 4; ++q) acc[i][j][q] = 0.0f;

    const int lane = tid & 31, warp = tid >> 5;
    const int wm = (warp >> 2) * 64, wn = (warp & 3) * WN;
    const int NC = K / 32;

    loadStage(0, 0);
    loadStage(1, 32);

    for (int c = 0; c < NC; ++c) {
        asm volatile("cp.async.wait_group 1;" ::: "memory");
        __syncthreads();
        if (c + 2 < NC) loadStage((c + 2) % 3, (c + 2) * 32);
        else CP_COMMIT();

        const uint32_t aB = sbase + (uint32_t)(c % 3) * STAGE;
        const uint32_t bB = aB + 2u * A_BLK;
#pragma unroll
        for (int ks = 0; ks < 32; ks += 16) {
            uint32_t a0[4][4], a1[4][4], bh[NL][4], bl[NL][4];
#pragma unroll
            for (int mi = 0; mi < 4; ++mi) {
                uint32_t ad = aB + (uint32_t)((wm + mi * 16 + (lane & 15)) * 40 + ks + (lane >> 4) * 8) * 2u;
                LDSMX4(a0[mi], ad);
            }
#pragma unroll
            for (int nj = 0; nj < NL; ++nj) {
                uint32_t bd = bB + (uint32_t)((ks + (lane & 15)) * BST + wn + nj * 16 + (lane >> 4) * 8) * 2u;
                LDSMX4T(bh[nj], bd);
            }
#pragma unroll
            for (int mi = 0; mi < 4; ++mi)
#pragma unroll
                for (int ni = 0; ni < NFR; ++ni)
                    MMA(acc[mi][ni], a0[mi], bh[ni >> 1][(ni & 1) * 2], bh[ni >> 1][(ni & 1) * 2 + 1]);
#pragma unroll
            for (int mi = 0; mi < 4; ++mi) {
                uint32_t ad = aB + A_BLK + (uint32_t)((wm + mi * 16 + (lane & 15)) * 40 + ks + (lane >> 4) * 8) * 2u;
                LDSMX4(a1[mi], ad);
            }
#pragma unroll
            for (int mi = 0; mi < 4; ++mi)
#pragma unroll
                for (int ni = 0; ni < NFR; ++ni)
                    MMA(acc[mi][ni], a1[mi], bh[ni >> 1][(ni & 1) * 2], bh[ni >> 1][(ni & 1) * 2 + 1]);
#pragma unroll
            for (int nj = 0; nj < NL; ++nj) {
                uint32_t bd = bB + B_BLK + (uint32_t)((ks + (lane & 15)) * BST + wn + nj * 16 + (lane >> 4) * 8) * 2u;
                LDSMX4T(bl[nj], bd);
            }
#pragma unroll
            for (int mi = 0; mi < 4; ++mi)
#pragma unroll
                for (int ni = 0; ni < NFR; ++ni)
                    MMA(acc[mi][ni], a0[mi], bl[ni >> 1][(ni & 1) * 2], bl[ni >> 1][(ni & 1) * 2 + 1]);
        }
    }

    // ---- fused epilogue ----
#pragma unroll
    for (int mi = 0; mi < 4; ++mi)
#pragma unroll
        for (int ni = 0; ni < NFR; ++ni) {
            int col = n0 + wn + ni * 8 + (lane & 3) * 2;
#pragma unroll
            for (int h = 0; h < 2; ++h) {
                int row = m0 + wm + mi * 16 + (lane >> 2) + h * 8;
                float vx = acc[mi][ni][h * 2], vy = acc[mi][ni][h * 2 + 1];
                long o = (long)row * ldc + col;
                if (EPI == 1) { vx -= XRp[o]; vy -= XRp[o + 1]; }
                if (EPI == 1 || EPI == 2) {
                    vx = fminf(fmaxf(vx, -1.0f), 1.0f);
                    vy = fminf(fmaxf(vy, -1.0f), 1.0f);
                    __half2 hh = *reinterpret_cast<const __half2*>(Hh + o);
                    __half2 ll = *reinterpret_cast<const __half2*>(Hl + o);
                    vx = (__half2float(__low2half(hh)) + __half2float(__low2half(ll))) - ALPHA_C * vx;
                    vy = (__half2float(__high2half(hh)) + __half2float(__high2half(ll))) - ALPHA_C * vy;
                }
                if (EPI == 3 && addI) {
                    if (row == col)     vx += 1.0f;
                    if (row == col + 1) vy += 1.0f;
                }
                if (EPI == 0 || ((EPI == 1 || EPI == 2) && Cf))
                    *reinterpret_cast<float2*>(Cf + o) = make_float2(vx, vy);
                if (EPI == 3 || ((EPI == 1 || EPI == 2) && Ch)) {
                    hf hx, lx, hy, ly;
                    hsplit(vx, hx, lx);
                    hsplit(vy, hy, ly);
                    *reinterpret_cast<uint32_t*>(Ch + o) = packh2(hx, hy);
                    *reinterpret_cast<uint32_t*>(Cl + o) = packh2(lx, ly);
                }
            }
        }
}

template <int BN>
constexpr uint32_t smemBytes() {
    return 3u * (2u * 10240u + 2u * (32u * (BN + 8u) * 2u));
}

} // namespace

extern "C" void kernel_launch(void* const* d_in, const int* in_sizes, int n_in,
                              void* d_out, int out_size)
{
    const float *x = nullptr, *W1 = nullptr, *W2 = nullptr, *h1 = nullptr, *h2 = nullptr;
    for (int i = 0; i < n_in; ++i) {
        switch (in_sizes[i]) {
            case 8388608: x  = (const float*)d_in[i]; break;
            case 262144:  W1 = (const float*)d_in[i]; break;
            case 65536:   W2 = (const float*)d_in[i]; break;
            case 4194304: h1 = (const float*)d_in[i]; break;
            case 2097152: h2 = (const float*)d_in[i]; break;
        }
    }
    float* out = (float*)d_out;

    unsigned char* pool;
    cudaGetSymbolAddress((void**)&pool, g_pool);
    size_t off = 0;
    auto grab = [&](size_t bytes) -> void* {
        void* p = pool + off;
        off = (off + bytes + 1023) & ~(size_t)1023;
        return p;
    };
    float* W1e   = (float*)grab(8388608);
    float* W1re  = (float*)grab(8388608);
    float* K1low = (float*)grab(2097152);
    float* K2top = (float*)grab(2097152);
    float* XR    = (float*)grab(16777216);
    hf* xh   = (hf*)grab(16777216); hf* xl   = (hf*)grab(16777216);
    hf* W1eh = (hf*)grab(4194304);  hf* W1el = (hf*)grab(4194304);
    hf* W1rh = (hf*)grab(4194304);  hf* W1rl = (hf*)grab(4194304);
    hf* H1h[2] = {(hf*)grab(8388608), (hf*)grab(8388608)};
    hf* H1l[2] = {(hf*)grab(8388608), (hf*)grab(8388608)};
    hf* H2h[2] = {(hf*)grab(4194304), (hf*)grab(4194304)};
    hf* H2l[2] = {(hf*)grab(4194304), (hf*)grab(4194304)};
    hf* K1h = (hf*)grab(3145728);  hf* K1l = (hf*)grab(3145728);
    hf* K2h = (hf*)grab(1572864);  hf* K2l = (hf*)grab(1572864);

    cudaFuncSetAttribute(hgemm<0, 256>, cudaFuncAttributeMaxDynamicSharedMemorySize, smemBytes<256>());
    cudaFuncSetAttribute(hgemm<1, 256>, cudaFuncAttributeMaxDynamicSharedMemorySize, smemBytes<256>());
    cudaFuncSetAttribute(hgemm<2, 128>, cudaFuncAttributeMaxDynamicSharedMemorySize, smemBytes<128>());
    cudaFuncSetAttribute(hgemm<3, 64>,  cudaFuncAttributeMaxDynamicSharedMemorySize, smemBytes<64>());

    const int NOSPLIT = 0x40000000;

    ExpandJobs E;
    E.W[0] = W1; E.out[0] = W1e;   E.J[0] = 128; E.I[0] = 256; E.rev[0] = 0; E.sgn[0] =  1.0f;
    E.W[1] = W1; E.out[1] = W1re;  E.J[1] = 256; E.I[1] = 128; E.rev[1] = 1; E.sgn[1] =  1.0f;
    E.W[2] = W2; E.out[2] = K1low; E.J[2] = 64;  E.I[2] = 128; E.rev[2] = 0; E.sgn[2] = -1.0f;
    E.W[3] = W2; E.out[3] = K2top; E.J[3] = 128; E.I[3] = 64;  E.rev[3] = 1; E.sgn[3] = -1.0f;
    E.start[0] = 0; E.start[1] = 8192; E.start[2] = 16384; E.start[3] = 18432; E.start[4] = 20480;
    expand_fused<<<20480, 256>>>(E);

    PackJobs P;
    P.src[0] = x;     P.hi[0] = xh;                 P.lo[0] = xl;
    P.src[1] = W1e;   P.hi[1] = W1eh;               P.lo[1] = W1el;
    P.src[2] = W1re;  P.hi[2] = W1rh;               P.lo[2] = W1rl;
    P.src[3] = h1;    P.hi[3] = H1h[0];             P.lo[3] = H1l[0];
    P.src[4] = h2;    P.hi[4] = H2h[0];             P.lo[4] = H2l[0];
    P.src[5] = K1low; P.hi[5] = K1h + 1024 * 1024;  P.lo[5] = K1l + 1024 * 1024;
    P.src[6] = K2top; P.hi[6] = K2h;                P.lo[6] = K2l;
    P.start[0] = 0;     P.start[1] = 8192;  P.start[2] = 10240; P.start[3] = 12288;
    P.start[4] = 16384; P.start[5] = 18432; P.start[6] = 18944; P.start[7] = 19456;
    pack_fused<<<19456, 256>>>(P);

    // XR = x @ What1r  [4096,1024], K=2048
    hgemm<0, 256><<<dim3(4, 32), 256, smemBytes<256>()>>>(
        xh, xl, 2048, nullptr, nullptr, 0, NOSPLIT,
        W1rh, W1rl, 1024, 2048, XR, 1024, nullptr, nullptr, nullptr, nullptr, nullptr, 0);
    // K1 top = What1@What1r + I  [1024,1024], K=2048
    hgemm<3, 64><<<dim3(16, 8), 256, smemBytes<64>()>>>(
        W1eh, W1el, 2048, nullptr, nullptr, 0, NOSPLIT,
        W1rh, W1rl, 1024, 2048, nullptr, 1024, nullptr, nullptr, nullptr, K1h, K1l, 1);
    // K2 bottom = (-What2)@(-What2r)  [512,512], K=1024
    hgemm<3, 64><<<dim3(8, 4), 256, smemBytes<64>()>>>(
        K1h + 1024 * 1024, K1l + 1024 * 1024, 1024, nullptr, nullptr, 0, NOSPLIT,
        K2h, K2l, 512, 1024, nullptr, 512, nullptr, nullptr, nullptr,
        K2h + 1024 * 512, K2l + 1024 * 512, 0);

    cudaMemcpyAsync(out, x, 33554432, cudaMemcpyDeviceToDevice, 0);
    float* out_h1 = out + 8388608;
    float* out_h2 = out + 12582912;

    for (int it = 0; it < 20; ++it) {
        int rd = it & 1, wr = 1 - rd;
        bool last = (it == 19);
        float* c1 = last ? out_h1 : nullptr;
        float* c2 = last ? out_h2 : nullptr;
        hf* p1h = H1h[wr]; hf* p1l = H1l[wr];
        hf* p2h = last ? nullptr : H2h[wr];
        hf* p2l = last ? nullptr : H2l[wr];
        // H1' = H1 - a*clip([H1|H2]@K1 - XR)   [4096,1024], K=1536
        hgemm<1, 256><<<dim3(4, 32), 256, smemBytes<256>()>>>(
            H1h[rd], H1l[rd], 1024, H2h[rd], H2l[rd], 512, 1024,
            K1h, K1l, 1024, 1536, c1, 1024, XR, H1h[rd], H1l[rd], p1h, p1l, 0);
        // H2' = H2 - a*clip([H1'|H2]@K2)       [4096,512], K=1536
        hgemm<2, 128><<<dim3(4, 32), 256, smemBytes<128>()>>>(
            H1h[wr], H1l[wr], 1024, H2h[rd], H2l[rd], 512, 1024,
            K2h, K2l, 512, 1536, c2, 512, nullptr, H2h[rd], H2l[rd], p2h, p2l, 0);
    }
}

// round 15
// speedup vs baseline: 3.2676x; 1.2870x over previous
#include <cuda_runtime.h>
#include <cuda_fp16.h>
#include <cstdint>

namespace {

constexpr float ALPHA_C = 0.01f;
typedef __half hf;

__device__ __align__(1024) unsigned char g_pool[200u * 1024u * 1024u];

__device__ __forceinline__ uint32_t smem_u32(const void* p) {
    uint32_t a;
    asm("{ .reg .u64 t; cvta.to.shared.u64 t, %1; cvt.u32.u64 %0, t; }" : "=r"(a) : "l"(p));
    return a;
}
__device__ __forceinline__ void cp16(uint32_t s, const void* g) {
    asm volatile("cp.async.cg.shared.global [%0], [%1], 16;" :: "r"(s), "l"(g) : "memory");
}
#define CP_COMMIT() asm volatile("cp.async.commit_group;" ::: "memory")
#define LDSMX4(r, addr) \
    asm volatile("ldmatrix.sync.aligned.m8n8.x4.shared.b16 {%0,%1,%2,%3}, [%4];" \
        : "=r"((r)[0]), "=r"((r)[1]), "=r"((r)[2]), "=r"((r)[3]) : "r"(addr))
#define LDSMX4T(r, addr) \
    asm volatile("ldmatrix.sync.aligned.m8n8.x4.trans.shared.b16 {%0,%1,%2,%3}, [%4];" \
        : "=r"((r)[0]), "=r"((r)[1]), "=r"((r)[2]), "=r"((r)[3]) : "r"(addr))
#define MMA(c, a, b0, b1) \
    asm volatile("mma.sync.aligned.m16n8k16.row.col.f32.f16.f16.f32 " \
        "{%0,%1,%2,%3}, {%4,%5,%6,%7}, {%8,%9}, {%0,%1,%2,%3};" \
        : "+f"((c)[0]), "+f"((c)[1]), "+f"((c)[2]), "+f"((c)[3]) \
        : "r"((a)[0]), "r"((a)[1]), "r"((a)[2]), "r"((a)[3]), "r"(b0), "r"(b1))

__device__ __forceinline__ void hsplit(float v, hf& h, hf& l) {
    h = __float2half_rn(v);
    l = __float2half_rn(v - __half2float(h));
}
__device__ __forceinline__ uint32_t packh2(hf a, hf b) {
    __half2 p = __halves2half2(a, b);
    return *reinterpret_cast<uint32_t*>(&p);
}

// ---------------- fused Cayley expansion (validated) ----------------
struct ExpandJobs {
    const float* W[4]; float* out[4];
    int J[4], I[4], rev[4]; float sgn[4]; int start[5];
};
__device__ __forceinline__ int reorder_sign(int a, int b) {
    int s = 0; int aa = a >> 1;
    while (aa) { s += __popc(aa & b); aa >>= 1; }
    return (s & 1) ? -1 : 1;
}
__global__ void expand_fused(ExpandJobs E)
{
    int blk = blockIdx.x, jb = 0;
#pragma unroll
    for (int t = 1; t < 4; ++t) if (blk >= E.start[t]) jb = t;
    int J = E.J[jb], I = E.I[jb];
    int idx = (blk - E.start[jb]) * 256 + threadIdx.x;
    int ncol = I * 8;
    int col = idx % ncol, row = idx / ncol;
    int a = row & 7, j = row >> 3, c = col & 7, i = col >> 3, e = a ^ c;
    float s = (float)reorder_sign(a, e) * E.sgn[jb];
    size_t widx;
    if (E.rev[jb]) {
        int k = __popc(e);
        if ((k * (k - 1) / 2) & 1) s = -s;
        widx = (size_t)j * ncol + (size_t)i * 8 + e;
    } else {
        widx = (size_t)i * (size_t)(J * 8) + (size_t)j * 8 + e;
    }
    E.out[jb][idx] = s * E.W[jb][widx];
}

// ---------------- fused fp32 -> fp16 hi/lo packer ----------------
struct PackJobs {
    const float* src[7]; hf* hi[7]; hf* lo[7]; int start[8];
};
__global__ void pack_fused(PackJobs P)
{
    int blk = blockIdx.x, jb = 0;
#pragma unroll
    for (int t = 1; t < 7; ++t) if (blk >= P.start[t]) jb = t;
    long i = ((long)(blk - P.start[jb]) * 256 + threadIdx.x) * 4;
    float4 v = *reinterpret_cast<const float4*>(P.src[jb] + i);
    hf h0, l0, h1, l1, h2, l2, h3, l3;
    hsplit(v.x, h0, l0); hsplit(v.y, h1, l1);
    hsplit(v.z, h2, l2); hsplit(v.w, h3, l3);
    *reinterpret_cast<uint2*>(P.hi[jb] + i) = make_uint2(packh2(h0, h1), packh2(h2, h3));
    *reinterpret_cast<uint2*>(P.lo[jb] + i) = make_uint2(packh2(l0, l1), packh2(l2, l3));
}

// ---------------------------------------------------------------------------
// fp16 mma.sync GEMM: C[m,n] = sum_k A[m,k]*B[k,n], A=[A0|A1] along K.
// A is always an fp16 hi/lo pair. BPAIR=1: B also pair (3-term, prologue
// accuracy). BPAIR=0: B single fp16 (2-term — weight-quant error is damped
// by ALPHA over the iteration, see round theory).
// CTA 128 x BN, 8 warps (2M x 4N), 3-stage cp.async, 1 sync per 32-k chunk.
// EPI 0: Cf = acc                                        (XR)
// EPI 1: g=clip(acc-XR); v=(Hh+Hl)-a*g; [Cf],[Ch/Cl]     (H1 update)
// EPI 2: g=clip(acc);    v=(Hh+Hl)-a*g; [Cf],[Ch/Cl]     (H2 update)
// EPI 3: v=acc(+I if addI); Ch (+Cl if given)            (M1/M2 weights)
// ---------------------------------------------------------------------------
template <int EPI, int BN, int BPAIR>
__global__ __launch_bounds__(256, 1) void hgemm(
    const hf* __restrict__ A0h, const hf* __restrict__ A0l, int lda0,
    const hf* __restrict__ A1h, const hf* __restrict__ A1l, int lda1, int ksplit,
    const hf* __restrict__ Bh, const hf* __restrict__ Bl, int ldb, int K,
    float* __restrict__ Cf, int ldc,
    const float* __restrict__ XRp,
    const hf* __restrict__ Hh, const hf* __restrict__ Hl,
    hf* __restrict__ Ch, hf* __restrict__ Cl, int addI)
{
    constexpr int WN  = BN / 4;
    constexpr int NFR = WN / 8;
    constexpr int NL  = NFR / 2;
    constexpr uint32_t BST   = BN + 8;
    constexpr uint32_t A_BLK = 10240u;
    constexpr uint32_t B_BLK = 32u * BST * 2u;
    constexpr uint32_t STAGE = 2u * A_BLK + (1u + BPAIR) * B_BLK;
    constexpr int CPT = BN / 64;
    constexpr int BROW = BN / 8;

    extern __shared__ unsigned char smdyn[];
    const uint32_t sbase = smem_u32(smdyn);
    const int tid = threadIdx.x;
    const int m0 = blockIdx.y * 128, n0 = blockIdx.x * BN;

    auto loadStage = [&](int s, int kt) {
        const hf *Ah, *Al;
        int lda, kk;
        if (kt < ksplit) { Ah = A0h; Al = A0l; lda = lda0; kk = kt; }
        else             { Ah = A1h; Al = A1l; lda = lda1; kk = kt - ksplit; }
        const uint32_t sa = sbase + (uint32_t)s * STAGE;
#pragma unroll
        for (int j = 0; j < 2; ++j) {
            int t = tid + j * 256;
            int row = t >> 2, c = (t & 3) * 8;
            long go = (long)(m0 + row) * lda + kk + c;
            uint32_t so = sa + (uint32_t)(row * 40 + c) * 2u;
            cp16(so, Ah + go);
            cp16(so + A_BLK, Al + go);
        }
        const uint32_t sb = sa + 2u * A_BLK;
#pragma unroll
        for (int j = 0; j < CPT; ++j) {
            int t = tid + j * 256;
            int row = t / BROW, c = (t % BROW) * 8;
            long go = (long)(kt + row) * ldb + n0 + c;
            uint32_t so = sb + (uint32_t)(row * BST + c) * 2u;
            cp16(so, Bh + go);
            if (BPAIR) cp16(so + B_BLK, Bl + go);
        }
        CP_COMMIT();
    };

    float acc[4][NFR][4];
#pragma unroll
    for (int i = 0; i < 4; ++i)
#pragma unroll
        for (int j = 0; j < NFR; ++j)
#pragma unroll
            for (int q = 0; q < 4; ++q) acc[i][j][q] = 0.0f;

    const int lane = tid & 31, warp = tid >> 5;
    const int wm = (warp >> 2) * 64, wn = (warp & 3) * WN;
    const int NC = K / 32;

    loadStage(0, 0);
    loadStage(1, 32);

    for (int c = 0; c < NC; ++c) {
        asm volatile("cp.async.wait_group 1;" ::: "memory");
        __syncthreads();
        if (c + 2 < NC) loadStage((c + 2) % 3, (c + 2) * 32);
        else CP_COMMIT();

        const uint32_t aB = sbase + (uint32_t)(c % 3) * STAGE;
        const uint32_t bB = aB + 2u * A_BLK;
#pragma unroll
        for (int ks = 0; ks < 32; ks += 16) {
            uint32_t a0[4][4], a1[4][4], bh[NL][4], bl[NL][4];
#pragma unroll
            for (int mi = 0; mi < 4; ++mi) {
                uint32_t ad = aB + (uint32_t)((wm + mi * 16 + (lane & 15)) * 40 + ks + (lane >> 4) * 8) * 2u;
                LDSMX4(a0[mi], ad);
            }
#pragma unroll
            for (int nj = 0; nj < NL; ++nj) {
                uint32_t bd = bB + (uint32_t)((ks + (lane & 15)) * BST + wn + nj * 16 + (lane >> 4) * 8) * 2u;
                LDSMX4T(bh[nj], bd);
            }
#pragma unroll
            for (int mi = 0; mi < 4; ++mi)
#pragma unroll
                for (int ni = 0; ni < NFR; ++ni)
                    MMA(acc[mi][ni], a0[mi], bh[ni >> 1][(ni & 1) * 2], bh[ni >> 1][(ni & 1) * 2 + 1]);
#pragma unroll
            for (int mi = 0; mi < 4; ++mi) {
                uint32_t ad = aB + A_BLK + (uint32_t)((wm + mi * 16 + (lane & 15)) * 40 + ks + (lane >> 4) * 8) * 2u;
                LDSMX4(a1[mi], ad);
            }
#pragma unroll
            for (int mi = 0; mi < 4; ++mi)
#pragma unroll
                for (int ni = 0; ni < NFR; ++ni)
                    MMA(acc[mi][ni], a1[mi], bh[ni >> 1][(ni & 1) * 2], bh[ni >> 1][(ni & 1) * 2 + 1]);
            if (BPAIR) {
#pragma unroll
                for (int nj = 0; nj < NL; ++nj) {
                    uint32_t bd = bB + B_BLK + (uint32_t)((ks + (lane & 15)) * BST + wn + nj * 16 + (lane >> 4) * 8) * 2u;
                    LDSMX4T(bl[nj], bd);
                }
#pragma unroll
                for (int mi = 0; mi < 4; ++mi)
#pragma unroll
                    for (int ni = 0; ni < NFR; ++ni)
                        MMA(acc[mi][ni], a0[mi], bl[ni >> 1][(ni & 1) * 2], bl[ni >> 1][(ni & 1) * 2 + 1]);
            }
        }
    }

    // ---- fused epilogue ----
#pragma unroll
    for (int mi = 0; mi < 4; ++mi)
#pragma unroll
        for (int ni = 0; ni < NFR; ++ni) {
            int col = n0 + wn + ni * 8 + (lane & 3) * 2;
#pragma unroll
            for (int h = 0; h < 2; ++h) {
                int row = m0 + wm + mi * 16 + (lane >> 2) + h * 8;
                float vx = acc[mi][ni][h * 2], vy = acc[mi][ni][h * 2 + 1];
                long o = (long)row * ldc + col;
                if (EPI == 1) { vx -= XRp[o]; vy -= XRp[o + 1]; }
                if (EPI == 1 || EPI == 2) {
                    vx = fminf(fmaxf(vx, -1.0f), 1.0f);
                    vy = fminf(fmaxf(vy, -1.0f), 1.0f);
                    __half2 hh = *reinterpret_cast<const __half2*>(Hh + o);
                    __half2 ll = *reinterpret_cast<const __half2*>(Hl + o);
                    vx = (__half2float(__low2half(hh)) + __half2float(__low2half(ll))) - ALPHA_C * vx;
                    vy = (__half2float(__high2half(hh)) + __half2float(__high2half(ll))) - ALPHA_C * vy;
                }
                if (EPI == 3 && addI) {
                    if (row == col)     vx += 1.0f;
                    if (row == col + 1) vy += 1.0f;
                }
                if (EPI == 0 || ((EPI == 1 || EPI == 2) && Cf))
                    *reinterpret_cast<float2*>(Cf + o) = make_float2(vx, vy);
                if (EPI == 3 || ((EPI == 1 || EPI == 2) && Ch)) {
                    hf hx, lx, hy, ly;
                    hsplit(vx, hx, lx);
                    hsplit(vy, hy, ly);
                    *reinterpret_cast<uint32_t*>(Ch + o) = packh2(hx, hy);
                    if (EPI != 3 || Cl)
                        *reinterpret_cast<uint32_t*>(Cl + o) = packh2(lx, ly);
                }
            }
        }
}

template <int BN, int BPAIR>
constexpr uint32_t smemBytes() {
    return 3u * (2u * 10240u + (1u + BPAIR) * (32u * (BN + 8u) * 2u));
}

} // namespace

extern "C" void kernel_launch(void* const* d_in, const int* in_sizes, int n_in,
                              void* d_out, int out_size)
{
    const float *x = nullptr, *W1 = nullptr, *W2 = nullptr, *h1 = nullptr, *h2 = nullptr;
    for (int i = 0; i < n_in; ++i) {
        switch (in_sizes[i]) {
            case 8388608: x  = (const float*)d_in[i]; break;
            case 262144:  W1 = (const float*)d_in[i]; break;
            case 65536:   W2 = (const float*)d_in[i]; break;
            case 4194304: h1 = (const float*)d_in[i]; break;
            case 2097152: h2 = (const float*)d_in[i]; break;
        }
    }
    float* out = (float*)d_out;

    unsigned char* pool;
    cudaGetSymbolAddress((void**)&pool, g_pool);
    size_t off = 0;
    auto grab = [&](size_t bytes) -> void* {
        void* p = pool + off;
        off = (off + bytes + 1023) & ~(size_t)1023;
        return p;
    };
    float* W1e   = (float*)grab(8388608);
    float* W1re  = (float*)grab(8388608);
    float* K1low = (float*)grab(2097152);   // -What2   [512,1024]
    float* K2top = (float*)grab(2097152);   // -What2r  [1024,512]
    float* XR    = (float*)grab(16777216);
    hf* xh   = (hf*)grab(16777216); hf* xl   = (hf*)grab(16777216);
    hf* W1eh = (hf*)grab(4194304);  hf* W1el = (hf*)grab(4194304);
    hf* W1rh = (hf*)grab(4194304);  hf* W1rl = (hf*)grab(4194304);
    hf* H1h[2] = {(hf*)grab(8388608), (hf*)grab(8388608)};
    hf* H1l[2] = {(hf*)grab(8388608), (hf*)grab(8388608)};
    hf* H2h[2] = {(hf*)grab(4194304), (hf*)grab(4194304)};
    hf* H2l[2] = {(hf*)grab(4194304), (hf*)grab(4194304)};
    hf* K1h  = (hf*)grab(3145728);   // [1536,1024] single fp16
    hf* K2h  = (hf*)grab(1572864);   // [1536,512]  single fp16
    hf* nW2l = (hf*)grab(1048576);   // lo of -What2 pair (A of M2)
    hf* scrl = (hf*)grab(1048576);   // discarded lo of -What2r

    cudaFuncSetAttribute(hgemm<0, 256, 1>, cudaFuncAttributeMaxDynamicSharedMemorySize, smemBytes<256, 1>());
    cudaFuncSetAttribute(hgemm<1, 256, 0>, cudaFuncAttributeMaxDynamicSharedMemorySize, smemBytes<256, 0>());
    cudaFuncSetAttribute(hgemm<2, 128, 0>, cudaFuncAttributeMaxDynamicSharedMemorySize, smemBytes<128, 0>());
    cudaFuncSetAttribute(hgemm<3, 64, 0>,  cudaFuncAttributeMaxDynamicSharedMemorySize, smemBytes<64, 0>());

    const int NOSPLIT = 0x40000000;

    ExpandJobs E;
    E.W[0] = W1; E.out[0] = W1e;   E.J[0] = 128; E.I[0] = 256; E.rev[0] = 0; E.sgn[0] =  1.0f;
    E.W[1] = W1; E.out[1] = W1re;  E.J[1] = 256; E.I[1] = 128; E.rev[1] = 1; E.sgn[1] =  1.0f;
    E.W[2] = W2; E.out[2] = K1low; E.J[2] = 64;  E.I[2] = 128; E.rev[2] = 0; E.sgn[2] = -1.0f;
    E.W[3] = W2; E.out[3] = K2top; E.J[3] = 128; E.I[3] = 64;  E.rev[3] = 1; E.sgn[3] = -1.0f;
    E.start[0] = 0; E.start[1] = 8192; E.start[2] = 16384; E.start[3] = 18432; E.start[4] = 20480;
    expand_fused<<<20480, 256>>>(E);

    PackJobs P;
    P.src[0] = x;     P.hi[0] = xh;                  P.lo[0] = xl;
    P.src[1] = W1e;   P.hi[1] = W1eh;                P.lo[1] = W1el;
    P.src[2] = W1re;  P.hi[2] = W1rh;                P.lo[2] = W1rl;
    P.src[3] = h1;    P.hi[3] = H1h[0];              P.lo[3] = H1l[0];
    P.src[4] = h2;    P.hi[4] = H2h[0];              P.lo[4] = H2l[0];
    P.src[5] = K1low; P.hi[5] = K1h + 1024 * 1024;   P.lo[5] = nW2l;   // -What2: hi in K1, lo kept for M2's A
    P.src[6] = K2top; P.hi[6] = K2h;                 P.lo[6] = scrl;   // -What2r single (lo discarded)
    P.start[0] = 0;     P.start[1] = 8192;  P.start[2] = 10240; P.start[3] = 12288;
    P.start[4] = 16384; P.start[5] = 18432; P.start[6] = 18944; P.start[7] = 19456;
    pack_fused<<<19456, 256>>>(P);

    // XR = x @ What1r  [4096,1024], K=2048 — 3-term (undamped error path)
    hgemm<0, 256, 1><<<dim3(4, 32), 256, smemBytes<256, 1>()>>>(
        xh, xl, 2048, nullptr, nullptr, 0, NOSPLIT,
        W1rh, W1rl, 1024, 2048, XR, 1024, nullptr, nullptr, nullptr, nullptr, nullptr, 0);
    // M1 + I -> K1h top (single fp16)  [1024,1024], K=2048 — 2-term (B = W1rh single)
    hgemm<3, 64, 0><<<dim3(16, 8), 256, smemBytes<64, 0>()>>>(
        W1eh, W1el, 2048, nullptr, nullptr, 0, NOSPLIT,
        W1rh, nullptr, 1024, 2048, nullptr, 1024, nullptr, nullptr, nullptr, K1h, nullptr, 1);
    // M2 -> K2h bottom (single fp16)  [512,512], K=1024 — A = -What2 pair, B = -What2r single
    hgemm<3, 64, 0><<<dim3(8, 4), 256, smemBytes<64, 0>()>>>(
        K1h + 1024 * 1024, nW2l, 1024, nullptr, nullptr, 0, NOSPLIT,
        K2h, nullptr, 512, 1024, nullptr, 512, nullptr, nullptr, nullptr,
        K2h + 1024 * 512, nullptr, 0);

    cudaMemcpyAsync(out, x, 33554432, cudaMemcpyDeviceToDevice, 0);
    float* out_h1 = out + 8388608;
    float* out_h2 = out + 12582912;

    for (int it = 0; it < 20; ++it) {
        int rd = it & 1, wr = 1 - rd;
        bool last = (it == 19);
        float* c1 = last ? out_h1 : nullptr;
        float* c2 = last ? out_h2 : nullptr;
        hf* p1h = H1h[wr]; hf* p1l = H1l[wr];
        hf* p2h = last ? nullptr : H2h[wr];
        hf* p2l = last ? nullptr : H2l[wr];
        // H1' = H1 - a*clip([H1|H2]@K1 - XR)   [4096,1024], K=1536 — 2-term
        hgemm<1, 256, 0><<<dim3(4, 32), 256, smemBytes<256, 0>()>>>(
            H1h[rd], H1l[rd], 1024, H2h[rd], H2l[rd], 512, 1024,
            K1h, nullptr, 1024, 1536, c1, 1024, XR, H1h[rd], H1l[rd], p1h, p1l, 0);
        // H2' = H2 - a*clip([H1'|H2]@K2)       [4096,512], K=1536 — 2-term
        hgemm<2, 128, 0><<<dim3(4, 32), 256, smemBytes<128, 0>()>>>(
            H1h[wr], H1l[wr], 1024, H2h[rd], H2l[rd], 512, 1024,
            K2h, nullptr, 512, 1536, c2, 512, nullptr, H2h[rd], H2l[rd], p2h, p2l, 0);
    }
}

// round 16
// speedup vs baseline: 4.3563x; 1.3332x over previous
#include <cuda_runtime.h>
#include <cuda_fp16.h>
#include <cstdint>

namespace {

constexpr float ALPHA_C = 0.01f;
typedef __half hf;

__device__ __align__(1024) unsigned char g_pool[220u * 1024u * 1024u];

__device__ __forceinline__ uint32_t smem_u32(const void* p) {
    uint32_t a;
    asm("{ .reg .u64 t; cvta.to.shared.u64 t, %1; cvt.u32.u64 %0, t; }" : "=r"(a) : "l"(p));
    return a;
}
__device__ __forceinline__ void cp16(uint32_t s, const void* g) {
    asm volatile("cp.async.cg.shared.global [%0], [%1], 16;" :: "r"(s), "l"(g) : "memory");
}
#define CP_COMMIT() asm volatile("cp.async.commit_group;" ::: "memory")
#define LDSMX4(r, addr) \
    asm volatile("ldmatrix.sync.aligned.m8n8.x4.shared.b16 {%0,%1,%2,%3}, [%4];" \
        : "=r"((r)[0]), "=r"((r)[1]), "=r"((r)[2]), "=r"((r)[3]) : "r"(addr))
#define LDSMX4T(r, addr) \
    asm volatile("ldmatrix.sync.aligned.m8n8.x4.trans.shared.b16 {%0,%1,%2,%3}, [%4];" \
        : "=r"((r)[0]), "=r"((r)[1]), "=r"((r)[2]), "=r"((r)[3]) : "r"(addr))
#define MMA(c, a, b0, b1) \
    asm volatile("mma.sync.aligned.m16n8k16.row.col.f32.f16.f16.f32 " \
        "{%0,%1,%2,%3}, {%4,%5,%6,%7}, {%8,%9}, {%0,%1,%2,%3};" \
        : "+f"((c)[0]), "+f"((c)[1]), "+f"((c)[2]), "+f"((c)[3]) \
        : "r"((a)[0]), "r"((a)[1]), "r"((a)[2]), "r"((a)[3]), "r"(b0), "r"(b1))

__device__ __forceinline__ void hsplit(float v, hf& h, hf& l) {
    h = __float2half_rn(v);
    l = __float2half_rn(v - __half2float(h));
}
__device__ __forceinline__ uint32_t packh2(hf a, hf b) {
    __half2 p = __halves2half2(a, b);
    return *reinterpret_cast<uint32_t*>(&p);
}

// ---------------- Cayley expansion (validated) ----------------
struct ExpandJobs {
    const float* W[4]; float* out[4];
    int J[4], I[4], rev[4]; float sgn[4]; int start[5];
};
__device__ __forceinline__ int reorder_sign(int a, int b) {
    int s = 0; int aa = a >> 1;
    while (aa) { s += __popc(aa & b); aa >>= 1; }
    return (s & 1) ? -1 : 1;
}
__global__ void expand_fused(ExpandJobs E)
{
    int blk = blockIdx.x, jb = 0;
#pragma unroll
    for (int t = 1; t < 4; ++t) if (blk >= E.start[t]) jb = t;
    int J = E.J[jb], I = E.I[jb];
    int idx = (blk - E.start[jb]) * 256 + threadIdx.x;
    int ncol = I * 8;
    int col = idx % ncol, row = idx / ncol;
    int a = row & 7, j = row >> 3, c = col & 7, i = col >> 3, e = a ^ c;
    float s = (float)reorder_sign(a, e) * E.sgn[jb];
    size_t widx;
    if (E.rev[jb]) {
        int k = __popc(e);
        if ((k * (k - 1) / 2) & 1) s = -s;
        widx = (size_t)j * ncol + (size_t)i * 8 + e;
    } else {
        widx = (size_t)i * (size_t)(J * 8) + (size_t)j * 8 + e;
    }
    E.out[jb][idx] = s * E.W[jb][widx];
}

// ---------------- fp32 -> fp16 hi/lo packer (signed) ----------------
struct PackJobs {
    const float* src[8]; hf* hi[8]; hf* lo[8]; float sgn[8]; int start[9];
};
__global__ void pack_fused(PackJobs P)
{
    int blk = blockIdx.x, jb = 0;
#pragma unroll
    for (int t = 1; t < 8; ++t) if (blk >= P.start[t]) jb = t;
    long i = ((long)(blk - P.start[jb]) * 256 + threadIdx.x) * 4;
    float4 v = *reinterpret_cast<const float4*>(P.src[jb] + i);
    float sg = P.sgn[jb];
    hf h0, l0, h1, l1, h2, l2, h3, l3;
    hsplit(sg * v.x, h0, l0); hsplit(sg * v.y, h1, l1);
    hsplit(sg * v.z, h2, l2); hsplit(sg * v.w, h3, l3);
    *reinterpret_cast<uint2*>(P.hi[jb] + i) = make_uint2(packh2(h0, h1), packh2(h2, h3));
    *reinterpret_cast<uint2*>(P.lo[jb] + i) = make_uint2(packh2(l0, l1), packh2(l2, l3));
}

// ---------------------------------------------------------------------------
// fp16 mma.sync GEMM, A = [A0|A1|A2] along K (segments at ks1, ks2).
// APAIR: A hi/lo pair (2 rounds) ; BPAIR: +1 round with B-lo (3-term).
// CTA 128 x BN, 8 warps (2M x 4N), 3-stage cp.async.
// EPI 0: Cf = acc (+ Add0 if non-null)                 (C1 / C2 constants)
// EPI 1: g=clip(acc+Cc+s); nd=s-a*g                    (D1 update, s=Dh+Dl)
// EPI 2: g=clip(acc+Cc);   nd=s-a*g                    (D2 update)
//        EPI1/2 write nDh/nDl pair; if Fout: Fout=Base+nd
// EPI 3: pair out (M1 / M2 weights)
// ---------------------------------------------------------------------------
template <int EPI, int BN, int APAIR, int BPAIR>
__global__ __launch_bounds__(256, 1) void hgemm(
    const hf* __restrict__ A0h, const hf* __restrict__ A0l, int lda0,
    const hf* __restrict__ A1h, const hf* __restrict__ A1l, int lda1, int ks1,
    const hf* __restrict__ A2h, const hf* __restrict__ A2l, int lda2, int ks2,
    const hf* __restrict__ Bh, const hf* __restrict__ Bl, int ldb, int K,
    float* __restrict__ Cf, const float* __restrict__ Cc,
    const float* __restrict__ Add0, int ldc,
    const hf* __restrict__ Dh, const hf* __restrict__ Dl,
    hf* __restrict__ nDh, hf* __restrict__ nDl,
    const float* __restrict__ Base, float* __restrict__ Fout)
{
    constexpr int WN  = BN / 4;
    constexpr int NFR = WN / 8;
    constexpr int NL  = NFR / 2;
    constexpr uint32_t BST   = BN + 8;
    constexpr uint32_t A_BLK = 10240u;
    constexpr uint32_t B_BLK = 32u * BST * 2u;
    constexpr uint32_t STAGE = (1u + APAIR) * A_BLK + (1u + BPAIR) * B_BLK;
    constexpr int CPT = BN / 64;
    constexpr int BROW = BN / 8;

    extern __shared__ unsigned char smdyn[];
    const uint32_t sbase = smem_u32(smdyn);
    const int tid = threadIdx.x;
    const int m0 = blockIdx.y * 128, n0 = blockIdx.x * BN;

    auto loadStage = [&](int s, int kt) {
        const hf *Ah, *Al;
        int lda, kk;
        if (kt < ks1)      { Ah = A0h; Al = A0l; lda = lda0; kk = kt; }
        else if (kt < ks2) { Ah = A1h; Al = A1l; lda = lda1; kk = kt - ks1; }
        else               { Ah = A2h; Al = A2l; lda = lda2; kk = kt - ks2; }
        const uint32_t sa = sbase + (uint32_t)s * STAGE;
#pragma unroll
        for (int j = 0; j < 2; ++j) {
            int t = tid + j * 256;
            int row = t >> 2, c = (t & 3) * 8;
            long go = (long)(m0 + row) * lda + kk + c;
            uint32_t so = sa + (uint32_t)(row * 40 + c) * 2u;
            cp16(so, Ah + go);
            if (APAIR) cp16(so + A_BLK, Al + go);
        }
        const uint32_t sb = sa + (1u + APAIR) * A_BLK;
#pragma unroll
        for (int j = 0; j < CPT; ++j) {
            int t = tid + j * 256;
            int row = t / BROW, c = (t % BROW) * 8;
            long go = (long)(kt + row) * ldb + n0 + c;
            uint32_t so = sb + (uint32_t)(row * BST + c) * 2u;
            cp16(so, Bh + go);
            if (BPAIR) cp16(so + B_BLK, Bl + go);
        }
        CP_COMMIT();
    };

    float acc[4][NFR][4];
#pragma unroll
    for (int i = 0; i < 4; ++i)
#pragma unroll
        for (int j = 0; j < NFR; ++j)
#pragma unroll
            for (int q = 0; q < 4; ++q) acc[i][j][q] = 0.0f;

    const int lane = tid & 31, warp = tid >> 5;
    const int wm = (warp >> 2) * 64, wn = (warp & 3) * WN;
    const int NC = K / 32;

    loadStage(0, 0);
    loadStage(1, 32);

    for (int c = 0; c < NC; ++c) {
        asm volatile("cp.async.wait_group 1;" ::: "memory");
        __syncthreads();
        if (c + 2 < NC) loadStage((c + 2) % 3, (c + 2) * 32);
        else CP_COMMIT();

        const uint32_t aB = sbase + (uint32_t)(c % 3) * STAGE;
        const uint32_t bB = aB + (1u + APAIR) * A_BLK;
#pragma unroll
        for (int ks = 0; ks < 32; ks += 16) {
            uint32_t a0[4][4], a1[4][4], bh[NL][4], bl[NL][4];
#pragma unroll
            for (int mi = 0; mi < 4; ++mi) {
                uint32_t ad = aB + (uint32_t)((wm + mi * 16 + (lane & 15)) * 40 + ks + (lane >> 4) * 8) * 2u;
                LDSMX4(a0[mi], ad);
            }
#pragma unroll
            for (int nj = 0; nj < NL; ++nj) {
                uint32_t bd = bB + (uint32_t)((ks + (lane & 15)) * BST + wn + nj * 16 + (lane >> 4) * 8) * 2u;
                LDSMX4T(bh[nj], bd);
            }
#pragma unroll
            for (int mi = 0; mi < 4; ++mi)
#pragma unroll
                for (int ni = 0; ni < NFR; ++ni)
                    MMA(acc[mi][ni], a0[mi], bh[ni >> 1][(ni & 1) * 2], bh[ni >> 1][(ni & 1) * 2 + 1]);
            if (APAIR) {
#pragma unroll
                for (int mi = 0; mi < 4; ++mi) {
                    uint32_t ad = aB + A_BLK + (uint32_t)((wm + mi * 16 + (lane & 15)) * 40 + ks + (lane >> 4) * 8) * 2u;
                    LDSMX4(a1[mi], ad);
                }
#pragma unroll
                for (int mi = 0; mi < 4; ++mi)
#pragma unroll
                    for (int ni = 0; ni < NFR; ++ni)
                        MMA(acc[mi][ni], a1[mi], bh[ni >> 1][(ni & 1) * 2], bh[ni >> 1][(ni & 1) * 2 + 1]);
            }
            if (BPAIR) {
#pragma unroll
                for (int nj = 0; nj < NL; ++nj) {
                    uint32_t bd = bB + B_BLK + (uint32_t)((ks + (lane & 15)) * BST + wn + nj * 16 + (lane >> 4) * 8) * 2u;
                    LDSMX4T(bl[nj], bd);
                }
#pragma unroll
                for (int mi = 0; mi < 4; ++mi)
#pragma unroll
                    for (int ni = 0; ni < NFR; ++ni)
                        MMA(acc[mi][ni], a0[mi], bl[ni >> 1][(ni & 1) * 2], bl[ni >> 1][(ni & 1) * 2 + 1]);
            }
        }
    }

    // ---- fused epilogue ----
#pragma unroll
    for (int mi = 0; mi < 4; ++mi)
#pragma unroll
        for (int ni = 0; ni < NFR; ++ni) {
            int col = n0 + wn + ni * 8 + (lane & 3) * 2;
#pragma unroll
            for (int h = 0; h < 2; ++h) {
                int row = m0 + wm + mi * 16 + (lane >> 2) + h * 8;
                float vx = acc[mi][ni][h * 2], vy = acc[mi][ni][h * 2 + 1];
                long o = (long)row * ldc + col;
                if (EPI == 0) {
                    if (Add0) { vx += Add0[o]; vy += Add0[o + 1]; }
                    *reinterpret_cast<float2*>(Cf + o) = make_float2(vx, vy);
                } else if (EPI == 1 || EPI == 2) {
                    float2 cc = *reinterpret_cast<const float2*>(Cc + o);
                    __half2 dh = *reinterpret_cast<const __half2*>(Dh + o);
                    __half2 dl = *reinterpret_cast<const __half2*>(Dl + o);
                    float sx = __half2float(__low2half(dh)) + __half2float(__low2half(dl));
                    float sy = __half2float(__high2half(dh)) + __half2float(__high2half(dl));
                    vx += cc.x; vy += cc.y;
                    if (EPI == 1) { vx += sx; vy += sy; }
                    vx = fminf(fmaxf(vx, -1.0f), 1.0f);
                    vy = fminf(fmaxf(vy, -1.0f), 1.0f);
                    float nx = sx - ALPHA_C * vx;
                    float ny = sy - ALPHA_C * vy;
                    hf hx, lx, hy, ly;
                    hsplit(nx, hx, lx);
                    hsplit(ny, hy, ly);
                    *reinterpret_cast<uint32_t*>(nDh + o) = packh2(hx, hy);
                    *reinterpret_cast<uint32_t*>(nDl + o) = packh2(lx, ly);
                    if (Fout) {
                        float2 b = *reinterpret_cast<const float2*>(Base + o);
                        *reinterpret_cast<float2*>(Fout + o) = make_float2(b.x + nx, b.y + ny);
                    }
                } else {  // EPI 3: pair output
                    hf hx, lx, hy, ly;
                    hsplit(vx, hx, lx);
                    hsplit(vy, hy, ly);
                    *reinterpret_cast<uint32_t*>(nDh + o) = packh2(hx, hy);
                    *reinterpret_cast<uint32_t*>(nDl + o) = packh2(lx, ly);
                }
            }
        }
}

constexpr uint32_t smemB(int BN, int AP, int BP) {
    return 3u * ((uint32_t)(1 + AP) * 10240u + (uint32_t)(1 + BP) * (32u * (BN + 8u) * 2u));
}

} // namespace

extern "C" void kernel_launch(void* const* d_in, const int* in_sizes, int n_in,
                              void* d_out, int out_size)
{
    const float *x = nullptr, *W1 = nullptr, *W2 = nullptr, *h1 = nullptr, *h2 = nullptr;
    for (int i = 0; i < n_in; ++i) {
        switch (in_sizes[i]) {
            case 8388608: x  = (const float*)d_in[i]; break;
            case 262144:  W1 = (const float*)d_in[i]; break;
            case 65536:   W2 = (const float*)d_in[i]; break;
            case 4194304: h1 = (const float*)d_in[i]; break;
            case 2097152: h2 = (const float*)d_in[i]; break;
        }
    }
    float* out = (float*)d_out;

    unsigned char* pool;
    cudaGetSymbolAddress((void**)&pool, g_pool);
    size_t off = 0;
    auto grab = [&](size_t bytes) -> void* {
        void* p = pool + off;
        off = (off + bytes + 1023) & ~(size_t)1023;
        return p;
    };
    float* W1e   = (float*)grab(8388608);   // What1   [1024,2048]
    float* W1re  = (float*)grab(8388608);   // What1r  [2048,1024]
    float* K1low = (float*)grab(2097152);   // -What2  [512,1024]
    float* K2top = (float*)grab(2097152);   // -What2r [1024,512]
    float* C1    = (float*)grab(16777216);  // [4096,1024]
    float* C2    = (float*)grab(8388608);   // [4096,512]
    hf* xh   = (hf*)grab(16777216); hf* xl   = (hf*)grab(16777216);
    hf* W1eh = (hf*)grab(4194304);  hf* W1el = (hf*)grab(4194304);
    hf* W1rh = (hf*)grab(4194304);  hf* W1rl = (hf*)grab(4194304);
    hf* H1h = (hf*)grab(8388608);   hf* H1l = (hf*)grab(8388608);
    hf* H2h = (hf*)grab(4194304);   hf* H2l = (hf*)grab(4194304);
    // BC1: [[M1],[−W2],[−W1r]] pair  [3584,1024]
    hf* BC1h = (hf*)grab(7340032);  hf* BC1l = (hf*)grab(7340032);
    // BC2: [[−W2r],[M2]] pair  [1536,512]
    hf* BC2h = (hf*)grab(1572864);  hf* BC2l = (hf*)grab(1572864);
    // Delta state (ping-pong pairs)
    hf* D1h[2] = {(hf*)grab(8388608), (hf*)grab(8388608)};
    hf* D1l[2] = {(hf*)grab(8388608), (hf*)grab(8388608)};
    hf* D2h[2] = {(hf*)grab(4194304), (hf*)grab(4194304)};
    hf* D2l[2] = {(hf*)grab(4194304), (hf*)grab(4194304)};

    cudaFuncSetAttribute(hgemm<3, 64, 1, 1>,  cudaFuncAttributeMaxDynamicSharedMemorySize, smemB(64, 1, 1));
    cudaFuncSetAttribute(hgemm<0, 256, 1, 1>, cudaFuncAttributeMaxDynamicSharedMemorySize, smemB(256, 1, 1));
    cudaFuncSetAttribute(hgemm<0, 128, 1, 1>, cudaFuncAttributeMaxDynamicSharedMemorySize, smemB(128, 1, 1));
    cudaFuncSetAttribute(hgemm<1, 256, 0, 0>, cudaFuncAttributeMaxDynamicSharedMemorySize, smemB(256, 0, 0));
    cudaFuncSetAttribute(hgemm<2, 128, 0, 0>, cudaFuncAttributeMaxDynamicSharedMemorySize, smemB(128, 0, 0));

    const int BIG = 0x40000000;

    ExpandJobs E;
    E.W[0] = W1; E.out[0] = W1e;   E.J[0] = 128; E.I[0] = 256; E.rev[0] = 0; E.sgn[0] =  1.0f;
    E.W[1] = W1; E.out[1] = W1re;  E.J[1] = 256; E.I[1] = 128; E.rev[1] = 1; E.sgn[1] =  1.0f;
    E.W[2] = W2; E.out[2] = K1low; E.J[2] = 64;  E.I[2] = 128; E.rev[2] = 0; E.sgn[2] = -1.0f;
    E.W[3] = W2; E.out[3] = K2top; E.J[3] = 128; E.I[3] = 64;  E.rev[3] = 1; E.sgn[3] = -1.0f;
    E.start[0] = 0; E.start[1] = 8192; E.start[2] = 16384; E.start[3] = 18432; E.start[4] = 20480;
    expand_fused<<<20480, 256>>>(E);

    PackJobs P;
    P.src[0] = x;     P.hi[0] = xh;                 P.lo[0] = xl;                 P.sgn[0] = 1.0f;
    P.src[1] = W1e;   P.hi[1] = W1eh;               P.lo[1] = W1el;               P.sgn[1] = 1.0f;
    P.src[2] = W1re;  P.hi[2] = W1rh;               P.lo[2] = W1rl;               P.sgn[2] = 1.0f;
    P.src[3] = h1;    P.hi[3] = H1h;                P.lo[3] = H1l;                P.sgn[3] = 1.0f;
    P.src[4] = h2;    P.hi[4] = H2h;                P.lo[4] = H2l;                P.sgn[4] = 1.0f;
    P.src[5] = K1low; P.hi[5] = BC1h + 1024 * 1024; P.lo[5] = BC1l + 1024 * 1024; P.sgn[5] = 1.0f;
    P.src[6] = W1re;  P.hi[6] = BC1h + 1536 * 1024; P.lo[6] = BC1l + 1536 * 1024; P.sgn[6] = -1.0f;
    P.src[7] = K2top; P.hi[7] = BC2h;               P.lo[7] = BC2l;               P.sgn[7] = 1.0f;
    P.start[0] = 0;     P.start[1] = 8192;  P.start[2] = 10240; P.start[3] = 12288;
    P.start[4] = 16384; P.start[5] = 18432; P.start[6] = 18944; P.start[7] = 20992;
    P.start[8] = 21504;
    pack_fused<<<21504, 256>>>(P);

    // zero the delta state (read before first write: D*[0] and D1*[1] pre-G1)
    cudaMemsetAsync(D1h[0], 0, 8388608, 0); cudaMemsetAsync(D1l[0], 0, 8388608, 0);
    cudaMemsetAsync(D2h[0], 0, 4194304, 0); cudaMemsetAsync(D2l[0], 0, 4194304, 0);

    // M1 = What1@What1r (no +I) -> BC1 rows 0..1023, pair  [1024,1024], K=2048
    hgemm<3, 64, 1, 1><<<dim3(16, 8), 256, smemB(64, 1, 1)>>>(
        W1eh, W1el, 2048, nullptr, nullptr, 0, BIG, nullptr, nullptr, 0, BIG,
        W1rh, W1rl, 1024, 2048, nullptr, nullptr, nullptr, 1024,
        nullptr, nullptr, BC1h, BC1l, nullptr, nullptr);
    // M2 = (-W2)@(-W2r) -> BC2 rows 1024..1535, pair  [512,512], K=1024
    hgemm<3, 64, 1, 1><<<dim3(8, 4), 256, smemB(64, 1, 1)>>>(
        BC1h + 1024 * 1024, BC1l + 1024 * 1024, 1024, nullptr, nullptr, 0, BIG,
        nullptr, nullptr, 0, BIG,
        BC2h, BC2l, 512, 1024, nullptr, nullptr, nullptr, 512,
        nullptr, nullptr, BC2h + 1024 * 512, BC2l + 1024 * 512, nullptr, nullptr);
    // C2 = [H1|H2] @ BC2  [4096,512], K=1536, 3-term
    hgemm<0, 128, 1, 1><<<dim3(4, 32), 256, smemB(128, 1, 1)>>>(
        H1h, H1l, 1024, H2h, H2l, 512, 1024, nullptr, nullptr, 0, BIG,
        BC2h, BC2l, 512, 1536, C2, nullptr, nullptr, 512,
        nullptr, nullptr, nullptr, nullptr, nullptr, nullptr);
    // C1 = [H1|H2|x] @ BC1 + H1_0  [4096,1024], K=3584, 3-term
    hgemm<0, 256, 1, 1><<<dim3(4, 32), 256, smemB(256, 1, 1)>>>(
        H1h, H1l, 1024, H2h, H2l, 512, 1024, xh, xl, 2048, 1536,
        BC1h, BC1l, 1024, 3584, C1, nullptr, h1, 1024,
        nullptr, nullptr, nullptr, nullptr, nullptr, nullptr);

    cudaMemcpyAsync(out, x, 33554432, cudaMemcpyDeviceToDevice, 0);
    float* out_h1 = out + 8388608;
    float* out_h2 = out + 12582912;

    for (int it = 0; it < 20; ++it) {
        int rd = it & 1, wr = 1 - rd;
        bool last = (it == 19);
        // D1' : g1 = clip(C1 + [D1|D2]@K1 + D1)   K=1536, 1-term
        hgemm<1, 256, 0, 0><<<dim3(4, 32), 256, smemB(256, 0, 0)>>>(
            D1h[rd], nullptr, 1024, D2h[rd], nullptr, 512, 1024,
            nullptr, nullptr, 0, BIG,
            BC1h, nullptr, 1024, 1536, nullptr, C1, nullptr, 1024,
            D1h[rd], D1l[rd], D1h[wr], D1l[wr], h1, last ? out_h1 : nullptr);
        // D2' : g2 = clip(C2 + [D1'|D2]@K2)       K=1536, 1-term
        hgemm<2, 128, 0, 0><<<dim3(4, 32), 256, smemB(128, 0, 0)>>>(
            D1h[wr], nullptr, 1024, D2h[rd], nullptr, 512, 1024,
            nullptr, nullptr, 0, BIG,
            BC2h, nullptr, 512, 1536, nullptr, C2, nullptr, 512,
            D2h[rd], D2l[rd], D2h[wr], D2l[wr], h2, last ? out_h2 : nullptr);
    }
}

// round 17
// speedup vs baseline: 4.5459x; 1.0435x over previous
#include <cuda_runtime.h>
#include <cuda_fp16.h>
#include <cstdint>

namespace {

constexpr float ALPHA_C = 0.01f;
typedef __half hf;

__device__ __align__(1024) unsigned char g_pool[220u * 1024u * 1024u];

__device__ __forceinline__ uint32_t smem_u32(const void* p) {
    uint32_t a;
    asm("{ .reg .u64 t; cvta.to.shared.u64 t, %1; cvt.u32.u64 %0, t; }" : "=r"(a) : "l"(p));
    return a;
}
__device__ __forceinline__ void cp16(uint32_t s, const void* g) {
    asm volatile("cp.async.cg.shared.global [%0], [%1], 16;" :: "r"(s), "l"(g) : "memory");
}
#define CP_COMMIT() asm volatile("cp.async.commit_group;" ::: "memory")
#define LDSMX4(r, addr) \
    asm volatile("ldmatrix.sync.aligned.m8n8.x4.shared.b16 {%0,%1,%2,%3}, [%4];" \
        : "=r"((r)[0]), "=r"((r)[1]), "=r"((r)[2]), "=r"((r)[3]) : "r"(addr))
#define LDSMX4T(r, addr) \
    asm volatile("ldmatrix.sync.aligned.m8n8.x4.trans.shared.b16 {%0,%1,%2,%3}, [%4];" \
        : "=r"((r)[0]), "=r"((r)[1]), "=r"((r)[2]), "=r"((r)[3]) : "r"(addr))
#define MMA(c, a, b0, b1) \
    asm volatile("mma.sync.aligned.m16n8k16.row.col.f32.f16.f16.f32 " \
        "{%0,%1,%2,%3}, {%4,%5,%6,%7}, {%8,%9}, {%0,%1,%2,%3};" \
        : "+f"((c)[0]), "+f"((c)[1]), "+f"((c)[2]), "+f"((c)[3]) \
        : "r"((a)[0]), "r"((a)[1]), "r"((a)[2]), "r"((a)[3]), "r"(b0), "r"(b1))

__device__ __forceinline__ void hsplit(float v, hf& h, hf& l) {
    h = __float2half_rn(v);
    l = __float2half_rn(v - __half2float(h));
}
__device__ __forceinline__ uint32_t packh2(hf a, hf b) {
    __half2 p = __halves2half2(a, b);
    return *reinterpret_cast<uint32_t*>(&p);
}

// ---------------- Cayley expansion (validated) ----------------
struct ExpandJobs {
    const float* W[4]; float* out[4];
    int J[4], I[4], rev[4]; float sgn[4]; int start[5];
};
__device__ __forceinline__ int reorder_sign(int a, int b) {
    int s = 0; int aa = a >> 1;
    while (aa) { s += __popc(aa & b); aa >>= 1; }
    return (s & 1) ? -1 : 1;
}
__global__ void expand_fused(ExpandJobs E)
{
    int blk = blockIdx.x, jb = 0;
#pragma unroll
    for (int t = 1; t < 4; ++t) if (blk >= E.start[t]) jb = t;
    int J = E.J[jb], I = E.I[jb];
    int idx = (blk - E.start[jb]) * 256 + threadIdx.x;
    int ncol = I * 8;
    int col = idx % ncol, row = idx / ncol;
    int a = row & 7, j = row >> 3, c = col & 7, i = col >> 3, e = a ^ c;
    float s = (float)reorder_sign(a, e) * E.sgn[jb];
    size_t widx;
    if (E.rev[jb]) {
        int k = __popc(e);
        if ((k * (k - 1) / 2) & 1) s = -s;
        widx = (size_t)j * ncol + (size_t)i * 8 + e;
    } else {
        widx = (size_t)i * (size_t)(J * 8) + (size_t)j * 8 + e;
    }
    E.out[jb][idx] = s * E.W[jb][widx];
}

// ---------------- fp32 -> fp16 hi/lo packer (signed) ----------------
struct PackJobs {
    const float* src[8]; hf* hi[8]; hf* lo[8]; float sgn[8]; int start[9];
};
__global__ void pack_fused(PackJobs P)
{
    int blk = blockIdx.x, jb = 0;
#pragma unroll
    for (int t = 1; t < 8; ++t) if (blk >= P.start[t]) jb = t;
    long i = ((long)(blk - P.start[jb]) * 256 + threadIdx.x) * 4;
    float4 v = *reinterpret_cast<const float4*>(P.src[jb] + i);
    float sg = P.sgn[jb];
    hf h0, l0, h1, l1, h2, l2, h3, l3;
    hsplit(sg * v.x, h0, l0); hsplit(sg * v.y, h1, l1);
    hsplit(sg * v.z, h2, l2); hsplit(sg * v.w, h3, l3);
    *reinterpret_cast<uint2*>(P.hi[jb] + i) = make_uint2(packh2(h0, h1), packh2(h2, h3));
    *reinterpret_cast<uint2*>(P.lo[jb] + i) = make_uint2(packh2(l0, l1), packh2(l2, l3));
}

// ---------------------------------------------------------------------------
// fp16 mma.sync GEMM, A = [A0|A1|A2] along K (segments at ks1, ks2).
// APAIR: A hi/lo pair (2 rounds) ; BPAIR: +1 round with B-lo (3-term).
// CTA 128 x BN, 8 warps (2M x 4N), 3-stage cp.async.
// EPI 0: Cf = acc (+ Add0 if non-null)                 (C1 / C2 constants)
// EPI 1: g=clip(acc+Cc+s); nd=s-a*g                    (D1 update, s=Dh+Dl)
// EPI 2: g=clip(acc+Cc);   nd=s-a*g                    (D2 update)
//        EPI1/2 write nDh/nDl pair; if Fout: Fout=Base+nd
// EPI 3: pair out (M1 / M2 weights)
// ---------------------------------------------------------------------------
template <int EPI, int BN, int APAIR, int BPAIR>
__global__ __launch_bounds__(256, 1) void hgemm(
    const hf* __restrict__ A0h, const hf* __restrict__ A0l, int lda0,
    const hf* __restrict__ A1h, const hf* __restrict__ A1l, int lda1, int ks1,
    const hf* __restrict__ A2h, const hf* __restrict__ A2l, int lda2, int ks2,
    const hf* __restrict__ Bh, const hf* __restrict__ Bl, int ldb, int K,
    float* __restrict__ Cf, const float* __restrict__ Cc,
    const float* __restrict__ Add0, int ldc,
    const hf* __restrict__ Dh, const hf* __restrict__ Dl,
    hf* __restrict__ nDh, hf* __restrict__ nDl,
    const float* __restrict__ Base, float* __restrict__ Fout)
{
    constexpr int WN  = BN / 4;
    constexpr int NFR = WN / 8;
    constexpr int NL  = NFR / 2;
    constexpr uint32_t BST   = BN + 8;
    constexpr uint32_t A_BLK = 10240u;
    constexpr uint32_t B_BLK = 32u * BST * 2u;
    constexpr uint32_t STAGE = (1u + APAIR) * A_BLK + (1u + BPAIR) * B_BLK;
    constexpr int CPT = BN / 64;
    constexpr int BROW = BN / 8;

    extern __shared__ unsigned char smdyn[];
    const uint32_t sbase = smem_u32(smdyn);
    const int tid = threadIdx.x;
    const int m0 = blockIdx.y * 128, n0 = blockIdx.x * BN;

    auto loadStage = [&](int s, int kt) {
        const hf *Ah, *Al;
        int lda, kk;
        if (kt < ks1)      { Ah = A0h; Al = A0l; lda = lda0; kk = kt; }
        else if (kt < ks2) { Ah = A1h; Al = A1l; lda = lda1; kk = kt - ks1; }
        else               { Ah = A2h; Al = A2l; lda = lda2; kk = kt - ks2; }
        const uint32_t sa = sbase + (uint32_t)s * STAGE;
#pragma unroll
        for (int j = 0; j < 2; ++j) {
            int t = tid + j * 256;
            int row = t >> 2, c = (t & 3) * 8;
            long go = (long)(m0 + row) * lda + kk + c;
            uint32_t so = sa + (uint32_t)(row * 40 + c) * 2u;
            cp16(so, Ah + go);
            if (APAIR) cp16(so + A_BLK, Al + go);
        }
        const uint32_t sb = sa + (1u + APAIR) * A_BLK;
#pragma unroll
        for (int j = 0; j < CPT; ++j) {
            int t = tid + j * 256;
            int row = t / BROW, c = (t % BROW) * 8;
            long go = (long)(kt + row) * ldb + n0 + c;
            uint32_t so = sb + (uint32_t)(row * BST + c) * 2u;
            cp16(so, Bh + go);
            if (BPAIR) cp16(so + B_BLK, Bl + go);
        }
        CP_COMMIT();
    };

    float acc[4][NFR][4];
#pragma unroll
    for (int i = 0; i < 4; ++i)
#pragma unroll
        for (int j = 0; j < NFR; ++j)
#pragma unroll
            for (int q = 0; q < 4; ++q) acc[i][j][q] = 0.0f;

    const int lane = tid & 31, warp = tid >> 5;
    const int wm = (warp >> 2) * 64, wn = (warp & 3) * WN;
    const int NC = K / 32;

    loadStage(0, 0);
    loadStage(1, 32);

    for (int c = 0; c < NC; ++c) {
        asm volatile("cp.async.wait_group 1;" ::: "memory");
        __syncthreads();
        if (c + 2 < NC) loadStage((c + 2) % 3, (c + 2) * 32);
        else CP_COMMIT();

        const uint32_t aB = sbase + (uint32_t)(c % 3) * STAGE;
        const uint32_t bB = aB + (1u + APAIR) * A_BLK;
#pragma unroll
        for (int ks = 0; ks < 32; ks += 16) {
            uint32_t a0[4][4], a1[4][4], bh[NL][4], bl[NL][4];
#pragma unroll
            for (int mi = 0; mi < 4; ++mi) {
                uint32_t ad = aB + (uint32_t)((wm + mi * 16 + (lane & 15)) * 40 + ks + (lane >> 4) * 8) * 2u;
                LDSMX4(a0[mi], ad);
            }
#pragma unroll
            for (int nj = 0; nj < NL; ++nj) {
                uint32_t bd = bB + (uint32_t)((ks + (lane & 15)) * BST + wn + nj * 16 + (lane >> 4) * 8) * 2u;
                LDSMX4T(bh[nj], bd);
            }
#pragma unroll
            for (int mi = 0; mi < 4; ++mi)
#pragma unroll
                for (int ni = 0; ni < NFR; ++ni)
                    MMA(acc[mi][ni], a0[mi], bh[ni >> 1][(ni & 1) * 2], bh[ni >> 1][(ni & 1) * 2 + 1]);
            if (APAIR) {
#pragma unroll
                for (int mi = 0; mi < 4; ++mi) {
                    uint32_t ad = aB + A_BLK + (uint32_t)((wm + mi * 16 + (lane & 15)) * 40 + ks + (lane >> 4) * 8) * 2u;
                    LDSMX4(a1[mi], ad);
                }
#pragma unroll
                for (int mi = 0; mi < 4; ++mi)
#pragma unroll
                    for (int ni = 0; ni < NFR; ++ni)
                        MMA(acc[mi][ni], a1[mi], bh[ni >> 1][(ni & 1) * 2], bh[ni >> 1][(ni & 1) * 2 + 1]);
            }
            if (BPAIR) {
#pragma unroll
                for (int nj = 0; nj < NL; ++nj) {
                    uint32_t bd = bB + B_BLK + (uint32_t)((ks + (lane & 15)) * BST + wn + nj * 16 + (lane >> 4) * 8) * 2u;
                    LDSMX4T(bl[nj], bd);
                }
#pragma unroll
                for (int mi = 0; mi < 4; ++mi)
#pragma unroll
                    for (int ni = 0; ni < NFR; ++ni)
                        MMA(acc[mi][ni], a0[mi], bl[ni >> 1][(ni & 1) * 2], bl[ni >> 1][(ni & 1) * 2 + 1]);
            }
        }
    }

    // ---- fused epilogue ----
#pragma unroll
    for (int mi = 0; mi < 4; ++mi)
#pragma unroll
        for (int ni = 0; ni < NFR; ++ni) {
            int col = n0 + wn + ni * 8 + (lane & 3) * 2;
#pragma unroll
            for (int h = 0; h < 2; ++h) {
                int row = m0 + wm + mi * 16 + (lane >> 2) + h * 8;
                float vx = acc[mi][ni][h * 2], vy = acc[mi][ni][h * 2 + 1];
                long o = (long)row * ldc + col;
                if (EPI == 0) {
                    if (Add0) { vx += Add0[o]; vy += Add0[o + 1]; }
                    *reinterpret_cast<float2*>(Cf + o) = make_float2(vx, vy);
                } else if (EPI == 1 || EPI == 2) {
                    float2 cc = *reinterpret_cast<const float2*>(Cc + o);
                    __half2 dh = *reinterpret_cast<const __half2*>(Dh + o);
                    __half2 dl = *reinterpret_cast<const __half2*>(Dl + o);
                    float sx = __half2float(__low2half(dh)) + __half2float(__low2half(dl));
                    float sy = __half2float(__high2half(dh)) + __half2float(__high2half(dl));
                    vx += cc.x; vy += cc.y;
                    if (EPI == 1) { vx += sx; vy += sy; }
                    vx = fminf(fmaxf(vx, -1.0f), 1.0f);
                    vy = fminf(fmaxf(vy, -1.0f), 1.0f);
                    float nx = sx - ALPHA_C * vx;
                    float ny = sy - ALPHA_C * vy;
                    hf hx, lx, hy, ly;
                    hsplit(nx, hx, lx);
                    hsplit(ny, hy, ly);
                    *reinterpret_cast<uint32_t*>(nDh + o) = packh2(hx, hy);
                    *reinterpret_cast<uint32_t*>(nDl + o) = packh2(lx, ly);
                    if (Fout) {
                        float2 b = *reinterpret_cast<const float2*>(Base + o);
                        *reinterpret_cast<float2*>(Fout + o) = make_float2(b.x + nx, b.y + ny);
                    }
                } else {  // EPI 3: pair output
                    hf hx, lx, hy, ly;
                    hsplit(vx, hx, lx);
                    hsplit(vy, hy, ly);
                    *reinterpret_cast<uint32_t*>(nDh + o) = packh2(hx, hy);
                    *reinterpret_cast<uint32_t*>(nDl + o) = packh2(lx, ly);
                }
            }
        }
}

constexpr uint32_t smemB(int BN, int AP, int BP) {
    return 3u * ((uint32_t)(1 + AP) * 10240u + (uint32_t)(1 + BP) * (32u * (BN + 8u) * 2u));
}

} // namespace

extern "C" void kernel_launch(void* const* d_in, const int* in_sizes, int n_in,
                              void* d_out, int out_size)
{
    const float *x = nullptr, *W1 = nullptr, *W2 = nullptr, *h1 = nullptr, *h2 = nullptr;
    for (int i = 0; i < n_in; ++i) {
        switch (in_sizes[i]) {
            case 8388608: x  = (const float*)d_in[i]; break;
            case 262144:  W1 = (const float*)d_in[i]; break;
            case 65536:   W2 = (const float*)d_in[i]; break;
            case 4194304: h1 = (const float*)d_in[i]; break;
            case 2097152: h2 = (const float*)d_in[i]; break;
        }
    }
    float* out = (float*)d_out;

    unsigned char* pool;
    cudaGetSymbolAddress((void**)&pool, g_pool);
    size_t off = 0;
    auto grab = [&](size_t bytes) -> void* {
        void* p = pool + off;
        off = (off + bytes + 1023) & ~(size_t)1023;
        return p;
    };
    float* W1e   = (float*)grab(8388608);   // What1   [1024,2048]
    float* W1re  = (float*)grab(8388608);   // What1r  [2048,1024]
    float* K1low = (float*)grab(2097152);   // -What2  [512,1024]
    float* K2top = (float*)grab(2097152);   // -What2r [1024,512]
    float* C1    = (float*)grab(16777216);  // [4096,1024]
    float* C2    = (float*)grab(8388608);   // [4096,512]
    hf* xh   = (hf*)grab(16777216); hf* xl   = (hf*)grab(16777216);
    hf* W1eh = (hf*)grab(4194304);  hf* W1el = (hf*)grab(4194304);
    hf* W1rh = (hf*)grab(4194304);  hf* W1rl = (hf*)grab(4194304);
    hf* H1h = (hf*)grab(8388608);   hf* H1l = (hf*)grab(8388608);
    hf* H2h = (hf*)grab(4194304);   hf* H2l = (hf*)grab(4194304);
    hf* BC1h = (hf*)grab(7340032);  hf* BC1l = (hf*)grab(7340032);  // [3584,1024]
    hf* BC2h = (hf*)grab(1572864);  hf* BC2l = (hf*)grab(1572864);  // [1536,512]
    hf* D1h[2] = {(hf*)grab(8388608), (hf*)grab(8388608)};
    hf* D1l[2] = {(hf*)grab(8388608), (hf*)grab(8388608)};
    hf* D2h[2] = {(hf*)grab(4194304), (hf*)grab(4194304)};
    hf* D2l[2] = {(hf*)grab(4194304), (hf*)grab(4194304)};

    cudaFuncSetAttribute(hgemm<3, 64, 1, 0>,  cudaFuncAttributeMaxDynamicSharedMemorySize, smemB(64, 1, 0));
    cudaFuncSetAttribute(hgemm<0, 256, 1, 0>, cudaFuncAttributeMaxDynamicSharedMemorySize, smemB(256, 1, 0));
    cudaFuncSetAttribute(hgemm<0, 128, 1, 0>, cudaFuncAttributeMaxDynamicSharedMemorySize, smemB(128, 1, 0));
    cudaFuncSetAttribute(hgemm<1, 256, 0, 0>, cudaFuncAttributeMaxDynamicSharedMemorySize, smemB(256, 0, 0));
    cudaFuncSetAttribute(hgemm<2, 128, 0, 0>, cudaFuncAttributeMaxDynamicSharedMemorySize, smemB(128, 0, 0));

    const int BIG = 0x40000000;

    ExpandJobs E;
    E.W[0] = W1; E.out[0] = W1e;   E.J[0] = 128; E.I[0] = 256; E.rev[0] = 0; E.sgn[0] =  1.0f;
    E.W[1] = W1; E.out[1] = W1re;  E.J[1] = 256; E.I[1] = 128; E.rev[1] = 1; E.sgn[1] =  1.0f;
    E.W[2] = W2; E.out[2] = K1low; E.J[2] = 64;  E.I[2] = 128; E.rev[2] = 0; E.sgn[2] = -1.0f;
    E.W[3] = W2; E.out[3] = K2top; E.J[3] = 128; E.I[3] = 64;  E.rev[3] = 1; E.sgn[3] = -1.0f;
    E.start[0] = 0; E.start[1] = 8192; E.start[2] = 16384; E.start[3] = 18432; E.start[4] = 20480;
    expand_fused<<<20480, 256>>>(E);

    PackJobs P;
    P.src[0] = x;     P.hi[0] = xh;                 P.lo[0] = xl;                 P.sgn[0] = 1.0f;
    P.src[1] = W1e;   P.hi[1] = W1eh;               P.lo[1] = W1el;               P.sgn[1] = 1.0f;
    P.src[2] = W1re;  P.hi[2] = W1rh;               P.lo[2] = W1rl;               P.sgn[2] = 1.0f;
    P.src[3] = h1;    P.hi[3] = H1h;                P.lo[3] = H1l;                P.sgn[3] = 1.0f;
    P.src[4] = h2;    P.hi[4] = H2h;                P.lo[4] = H2l;                P.sgn[4] = 1.0f;
    P.src[5] = K1low; P.hi[5] = BC1h + 1024 * 1024; P.lo[5] = BC1l + 1024 * 1024; P.sgn[5] = 1.0f;
    P.src[6] = W1re;  P.hi[6] = BC1h + 1536 * 1024; P.lo[6] = BC1l + 1536 * 1024; P.sgn[6] = -1.0f;
    P.src[7] = K2top; P.hi[7] = BC2h;               P.lo[7] = BC2l;               P.sgn[7] = 1.0f;
    P.start[0] = 0;     P.start[1] = 8192;  P.start[2] = 10240; P.start[3] = 12288;
    P.start[4] = 16384; P.start[5] = 18432; P.start[6] = 18944; P.start[7] = 20992;
    P.start[8] = 21504;
    pack_fused<<<21504, 256>>>(P);

    cudaMemsetAsync(D1h[0], 0, 8388608, 0); cudaMemsetAsync(D1l[0], 0, 8388608, 0);
    cudaMemsetAsync(D2h[0], 0, 4194304, 0); cudaMemsetAsync(D2l[0], 0, 4194304, 0);

    // M1 = What1@What1r -> BC1 rows 0..1023, pair out  [1024,1024], K=2048 — 2-term
    hgemm<3, 64, 1, 0><<<dim3(16, 8), 256, smemB(64, 1, 0)>>>(
        W1eh, W1el, 2048, nullptr, nullptr, 0, BIG, nullptr, nullptr, 0, BIG,
        W1rh, nullptr, 1024, 2048, nullptr, nullptr, nullptr, 1024,
        nullptr, nullptr, BC1h, BC1l, nullptr, nullptr);
    // M2 = (-W2)@(-W2r) -> BC2 rows 1024..1535, pair out  [512,512], K=1024 — 2-term
    hgemm<3, 64, 1, 0><<<dim3(8, 4), 256, smemB(64, 1, 0)>>>(
        BC1h + 1024 * 1024, BC1l + 1024 * 1024, 1024, nullptr, nullptr, 0, BIG,
        nullptr, nullptr, 0, BIG,
        BC2h, nullptr, 512, 1024, nullptr, nullptr, nullptr, 512,
        nullptr, nullptr, BC2h + 1024 * 512, BC2l + 1024 * 512, nullptr, nullptr);
    // C2 = [H1|H2] @ BC2  [4096,512], K=1536 — 2-term
    hgemm<0, 128, 1, 0><<<dim3(4, 32), 256, smemB(128, 1, 0)>>>(
        H1h, H1l, 1024, H2h, H2l, 512, 1024, nullptr, nullptr, 0, BIG,
        BC2h, nullptr, 512, 1536, C2, nullptr, nullptr, 512,
        nullptr, nullptr, nullptr, nullptr, nullptr, nullptr);
    // C1 = [H1|H2|x] @ BC1 + H1_0  [4096,1024], K=3584 — 2-term
    hgemm<0, 256, 1, 0><<<dim3(4, 32), 256, smemB(256, 1, 0)>>>(
        H1h, H1l, 1024, H2h, H2l, 512, 1024, xh, xl, 2048, 1536,
        BC1h, nullptr, 1024, 3584, C1, nullptr, h1, 1024,
        nullptr, nullptr, nullptr, nullptr, nullptr, nullptr);

    cudaMemcpyAsync(out, x, 33554432, cudaMemcpyDeviceToDevice, 0);
    float* out_h1 = out + 8388608;
    float* out_h2 = out + 12582912;

    for (int it = 0; it < 20; ++it) {
        int rd = it & 1, wr = 1 - rd;
        bool last = (it == 19);
        // D1' : g1 = clip(C1 + [D1|D2]@K1 + D1)   K=1536, 1-term
        hgemm<1, 256, 0, 0><<<dim3(4, 32), 256, smemB(256, 0, 0)>>>(
            D1h[rd], nullptr, 1024, D2h[rd], nullptr, 512, 1024,
            nullptr, nullptr, 0, BIG,
            BC1h, nullptr, 1024, 1536, nullptr, C1, nullptr, 1024,
            D1h[rd], D1l[rd], D1h[wr], D1l[wr], h1, last ? out_h1 : nullptr);
        // D2' : g2 = clip(C2 + [D1'|D2]@K2)       K=1536, 1-term
        hgemm<2, 128, 0, 0><<<dim3(4, 32), 256, smemB(128, 0, 0)>>>(
            D1h[wr], nullptr, 1024, D2h[rd], nullptr, 512, 1024,
            nullptr, nullptr, 0, BIG,
            BC2h, nullptr, 512, 1536, nullptr, C2, nullptr, 512,
            D2h[rd], D2l[rd], D2h[wr], D2l[wr], h2, last ? out_h2 : nullptr);
    }
}